// round 13
// baseline (speedup 1.0000x reference)
#include <cuda_runtime.h>
#include <cuda_fp16.h>
#include <cfloat>
#include <math.h>
#include <stdint.h>

// Problem constants
#define BATCH 8
#define SEQ   1024
#define DIM   1024
#define NHEAD 16
#define HDIM  64
#define FDIM  4096
#define TOK   (BATCH*SEQ)   // 8192

// ---------------- scratch (static device globals; no allocation) ----------------
__device__ __half g_ln  [(size_t)TOK * DIM];    // LN out (half, feeds GEMM)
__device__ float  g_ln32[(size_t)TOK * DIM];    // LN1 fp32 copy (FFN2 residual)
__device__ __half g_qkv [(size_t)TOK * 3*DIM];  // qkv (half — feeds fp16 attention)
__device__ __half g_att [(size_t)TOK * DIM];    // attention out (half)
__device__ float  g_x   [(size_t)TOK * DIM];    // src + proj(att) (fp32)
__device__ __half g_ffn [(size_t)TOK * FDIM];   // GELU(FFN1) (half)
__device__ int    g_msk [TOK];
// half weight copies
__device__ __half g_wq[(size_t)3*DIM*DIM];
__device__ __half g_wp[(size_t)DIM*DIM];
__device__ __half g_w1[(size_t)FDIM*DIM];
__device__ __half g_w2[(size_t)DIM*FDIM];

// ======================= small helpers =======================
__device__ __forceinline__ uint32_t smem_u32(const void* p) {
    uint32_t a;
    asm("{ .reg .u64 t; cvta.to.shared.u64 t, %1; cvt.u32.u64 %0, t; }" : "=r"(a) : "l"(p));
    return a;
}

__device__ __forceinline__ uint32_t h2_u32(__half2 h) {
    uint32_t u;
    memcpy(&u, &h, 4);
    return u;
}

__device__ __forceinline__ void mma_f16(float c[4],
                                        uint32_t a0, uint32_t a1, uint32_t a2, uint32_t a3,
                                        uint32_t b0, uint32_t b1) {
    asm volatile(
        "mma.sync.aligned.m16n8k16.row.col.f32.f16.f16.f32 "
        "{%0,%1,%2,%3}, {%4,%5,%6,%7}, {%8,%9}, {%0,%1,%2,%3};"
        : "+f"(c[0]), "+f"(c[1]), "+f"(c[2]), "+f"(c[3])
        : "r"(a0), "r"(a1), "r"(a2), "r"(a3), "r"(b0), "r"(b1));
}

#define LDSM_X4(r0, r1, r2, r3, addr) \
    asm volatile("ldmatrix.sync.aligned.m8n8.x4.shared.b16 {%0,%1,%2,%3}, [%4];" \
        : "=r"(r0), "=r"(r1), "=r"(r2), "=r"(r3) : "r"(addr))

#define CP_ASYNC16(saddr, gptr) \
    asm volatile("cp.async.cg.shared.global [%0], [%1], 16;" :: "r"(saddr), "l"(gptr))
#define CP_COMMIT() asm volatile("cp.async.commit_group;")
#define CP_WAIT1()  asm volatile("cp.async.wait_group 1;")
#define CP_WAIT0()  asm volatile("cp.async.wait_group 0;")

__device__ __forceinline__ float gelu_f(float x)
{
    return 0.5f * x * (1.0f + erff(x * 0.70710678118654752f));
}

// ---------------- fp32 -> fp16 conversion of ALL weights in one launch ----------------
__global__ void cvt_all_kernel(const float4* __restrict__ i0, __half2* __restrict__ o0, int n0,
                               const float4* __restrict__ i1, __half2* __restrict__ o1, int n1,
                               const float4* __restrict__ i2, __half2* __restrict__ o2, int n2,
                               const float4* __restrict__ i3, __half2* __restrict__ o3, int n3)
{
    int idx = blockIdx.x * blockDim.x + threadIdx.x;
    const float4* in; __half2* out;
    if (idx < n0)              { in = i0; out = o0; }
    else if ((idx -= n0) < n1) { in = i1; out = o1; }
    else if ((idx -= n1) < n2) { in = i2; out = o2; }
    else if ((idx -= n2) < n3) { in = i3; out = o3; }
    else return;
    float4 v = in[idx];
    out[2*idx]   = __floats2half2_rn(v.x, v.y);
    out[2*idx+1] = __floats2half2_rn(v.z, v.w);
}

// ---------------- mask dtype detection + normalization ----------------
__global__ void mask_kernel(const unsigned char* __restrict__ raw, int* __restrict__ gm)
{
    __shared__ int cnt[4];
    int t = threadIdx.x;
    if (t < 4) cnt[t] = 0;
    __syncthreads();
    int l1=0, l2=0, l3=0, lb=0;
    for (int i = t; i < TOK; i += blockDim.x) {
        unsigned char bch = raw[i];
        if (bch) {
            int m = i & 3;
            if (m == 1) l1++;
            else if (m == 2) l2++;
            else if (m == 3) l3++;
            if (bch > 1) lb++;
        }
    }
    atomicAdd(&cnt[0], l1); atomicAdd(&cnt[1], l2);
    atomicAdd(&cnt[2], l3); atomicAdd(&cnt[3], lb);
    __syncthreads();
    int c1 = cnt[0], c2 = cnt[1], c3 = cnt[2], cb = cnt[3];
    int type;
    if (c1 < 64 && c2 < 64 && c3 < 64) type = 0;
    else if (c1 < 64)                  type = 1;
    else if (cb < 64)                  type = 2;
    else                               type = 3;
    for (int i = t; i < TOK; i += blockDim.x) {
        int v;
        if      (type == 0) v = (((const int*)raw)[i] != 0);
        else if (type == 1) v = (((const float*)raw)[i] != 0.0f);
        else if (type == 2) v = (raw[i] != 0);
        else                v = (((const unsigned short*)raw)[i] != 0);
        gm[i] = v;
    }
}

// ---------------- LayerNorm: half out (+ optional fp32 copy) ----------------
template<bool WF>
__global__ void ln_kernel(const float* __restrict__ in,
                          const float* __restrict__ gamma,
                          const float* __restrict__ beta,
                          __half* __restrict__ outh,
                          float* __restrict__ outf)
{
    int row = blockIdx.x;
    int t = threadIdx.x;
    const float* xr = in + (size_t)row * DIM;
    float4 v = ((const float4*)xr)[t];
    float s = v.x + v.y + v.z + v.w;
    float q = v.x*v.x + v.y*v.y + v.z*v.z + v.w*v.w;
    #pragma unroll
    for (int o = 16; o; o >>= 1) {
        s += __shfl_xor_sync(0xffffffffu, s, o);
        q += __shfl_xor_sync(0xffffffffu, q, o);
    }
    __shared__ float ss[8], qq[8];
    if ((t & 31) == 0) { ss[t >> 5] = s; qq[t >> 5] = q; }
    __syncthreads();
    s = 0.f; q = 0.f;
    #pragma unroll
    for (int i = 0; i < 8; i++) { s += ss[i]; q += qq[i]; }
    float mean = s * (1.0f / DIM);
    float var  = q * (1.0f / DIM) - mean * mean;
    float rstd = rsqrtf(var + 1e-5f);
    float4 gv = ((const float4*)gamma)[t];
    float4 bv = ((const float4*)beta)[t];
    float ox = (v.x - mean) * rstd * gv.x + bv.x;
    float oy = (v.y - mean) * rstd * gv.y + bv.y;
    float oz = (v.z - mean) * rstd * gv.z + bv.z;
    float ow = (v.w - mean) * rstd * gv.w + bv.w;
    __half2* oh = (__half2*)(outh + (size_t)row * DIM);
    oh[2*t]   = __floats2half2_rn(ox, oy);
    oh[2*t+1] = __floats2half2_rn(oz, ow);
    if (WF) {
        float4 o = {ox, oy, oz, ow};
        ((float4*)(outf + (size_t)row * DIM))[t] = o;
    }
}

// ======================= FP16 mma.sync GEMM — 128x256 tile, warp 64x64 =======================
// C[M,N] = A[M,K] @ B[N,K]^T (+bias/gelu/res). 8 warps (2m x 4n), 2-stage (proven R11
// sync structure), ldmatrix fragments, row stride 20 half2 (80B).
// SMEM: [A s0 | A s1 | B s0 | B s1]; A stage 128 rows, B stage 256 rows.
#define SH2 20
#define HSTG_A (128*SH2)                  // 2560 half2
#define HSTG_Bm (256*SH2)                 // 5120 half2
#define HSTGA_B (HSTG_A*4)                // A stage bytes (10240)
#define HSTGB_B (HSTG_Bm*4)               // B stage bytes (20480)
#define GSMEM_BYTES ((2*HSTG_A + 2*HSTG_Bm)*4)   // 61440

template<int N, int K, bool HAS_BIAS, bool HAS_GELU, bool HAS_RES, bool OUT_HALF>
__global__ void __launch_bounds__(256, 1)
gemm_mma(const __half* __restrict__ A, const __half* __restrict__ Bm,
         const float* __restrict__ bias, const float* __restrict__ res,
         void* __restrict__ Cout)
{
    extern __shared__ __half2 sh[];
    __half2* As0 = sh;                    // A stages 0,1
    __half2* Bs0 = sh + 2*HSTG_A;         // B stages 0,1

    int tid  = threadIdx.x;
    int lane = tid & 31, warp = tid >> 5;
    int wm = warp >> 2, wn = warp & 3;
    int gid = lane >> 2, tig = lane & 3;
    int bm = blockIdx.y * 128, bn = blockIdx.x * 256;

    // loader: A = 128 rows x 4 segs (512 chunks, 2/thread); B = 256 rows x 4 segs (1024, 4/thread)
    int lrow = tid >> 2;          // 0..63
    int lseg = tid & 3;           // 0..3
    const __half* gA = A  + (size_t)(bm + lrow) * K + lseg * 8;
    const __half* gB = Bm + (size_t)(bn + lrow) * K + lseg * 8;
    uint32_t uA = smem_u32(&As0[lrow*SH2 + lseg*4]);
    uint32_t uB = smem_u32(&Bs0[lrow*SH2 + lseg*4]);
    const uint32_t SROW64 = 64u * SH2 * 4u;
    const size_t  GROW64 = (size_t)64 * K;

    // ldmatrix per-lane addresses (stage 0 base)
    int lane15 = lane & 15;
    int lq     = lane >> 4;
    uint32_t aAddr[4];
    #pragma unroll
    for (int mt = 0; mt < 4; mt++)
        aAddr[mt] = smem_u32(&As0[(wm*64 + mt*16 + lane15)*SH2]) + lq*16;
    uint32_t bAddr[4];
    {
        int quad = lane >> 3;
        int l7   = lane & 7;
        #pragma unroll
        for (int p = 0; p < 4; p++) {
            int row = wn*64 + (2*p + (quad >> 1))*8 + l7;
            bAddr[p] = smem_u32(&Bs0[row*SH2]) + (quad & 1)*16;
        }
    }

    float acc[4][8][4];
    #pragma unroll
    for (int mt = 0; mt < 4; mt++)
        #pragma unroll
        for (int nt = 0; nt < 8; nt++)
            #pragma unroll
            for (int e = 0; e < 4; e++) acc[mt][nt][e] = 0.f;

    const int KT = K / 32;

    // prefetch stage 0
    #pragma unroll
    for (int i = 0; i < 2; i++) CP_ASYNC16(uA + i*SROW64, gA + i*GROW64);
    #pragma unroll
    for (int i = 0; i < 4; i++) CP_ASYNC16(uB + i*SROW64, gB + i*GROW64);
    CP_COMMIT();

    for (int kt = 0; kt < KT; kt++) {
        int cur = kt & 1;
        if (kt + 1 < KT) {
            int nxt = cur ^ 1;
            size_t go = (size_t)(kt + 1) * 32;
            uint32_t soA = (uint32_t)nxt * HSTGA_B;
            uint32_t soB = (uint32_t)nxt * HSTGB_B;
            #pragma unroll
            for (int i = 0; i < 2; i++) CP_ASYNC16(uA + soA + i*SROW64, gA + go + i*GROW64);
            #pragma unroll
            for (int i = 0; i < 4; i++) CP_ASYNC16(uB + soB + i*SROW64, gB + go + i*GROW64);
            CP_COMMIT();
            CP_WAIT1();
        } else {
            CP_WAIT0();
        }
        __syncthreads();

        uint32_t stA = (uint32_t)cur * HSTGA_B;
        uint32_t stB = (uint32_t)cur * HSTGB_B;
        #pragma unroll
        for (int ks = 0; ks < 2; ks++) {
            uint32_t ko = ks * 32;
            uint32_t af[4][4];
            #pragma unroll
            for (int mt = 0; mt < 4; mt++)
                LDSM_X4(af[mt][0], af[mt][1], af[mt][2], af[mt][3],
                        aAddr[mt] + stA + ko);
            #pragma unroll
            for (int p = 0; p < 4; p++) {
                uint32_t b0, b1, b2, b3;
                LDSM_X4(b0, b1, b2, b3, bAddr[p] + stB + ko);
                #pragma unroll
                for (int mt = 0; mt < 4; mt++) {
                    mma_f16(acc[mt][2*p],   af[mt][0], af[mt][1], af[mt][2], af[mt][3], b0, b1);
                    mma_f16(acc[mt][2*p+1], af[mt][0], af[mt][1], af[mt][2], af[mt][3], b2, b3);
                }
            }
        }
        __syncthreads();
    }

    #pragma unroll
    for (int mt = 0; mt < 4; mt++) {
        int row = bm + wm*64 + mt*16 + gid;
        #pragma unroll
        for (int nt = 0; nt < 8; nt++) {
            int col = bn + wn*64 + nt*8 + 2*tig;
            float2 bb = {0.f, 0.f};
            if (HAS_BIAS) bb = *(const float2*)&bias[col];
            #pragma unroll
            for (int half_ = 0; half_ < 2; half_++) {
                int rr = row + half_*8;
                float vx = acc[mt][nt][half_*2+0];
                float vy = acc[mt][nt][half_*2+1];
                if (HAS_BIAS) { vx += bb.x; vy += bb.y; }
                if (HAS_GELU) { vx = gelu_f(vx); vy = gelu_f(vy); }
                if (HAS_RES) {
                    float2 rv = *(const float2*)&res[(size_t)rr * N + col];
                    vx += rv.x; vy += rv.y;
                }
                if (OUT_HALF) {
                    __half2* cp = (__half2*)((__half*)Cout + (size_t)rr * N + col);
                    *cp = __floats2half2_rn(vx, vy);
                } else {
                    float2 o2 = {vx, vy};
                    *(float2*)((float*)Cout + (size_t)rr * N + col) = o2;
                }
            }
        }
    }
}

// ======================= fp16 flash attention (proven in R11) =======================
#define ASQ2  0
#define ASK2  4608
#define ASV2  9216
#define ASVT2 13824
#define ASP2  16128
#define AH2TOT 20736
#define ATTN_BYTES (AH2TOT*4 + 2*64*4)   // 83456

__global__ void __launch_bounds__(256)
attn_mma(const __half* __restrict__ qkv, const int* __restrict__ gm,
         __half* __restrict__ outp)
{
    extern __shared__ __half2 S[];
    int* smk = (int*)(S + AH2TOT);

    const float SCALE = 0.125f;
    int tid = threadIdx.x, lane = tid & 31, warp = tid >> 5;
    int gid = lane >> 2, tig = lane & 3;
    int bh = blockIdx.y, b = bh >> 4, h = bh & 15;
    int q0 = blockIdx.x * 128;
    int qr = warp*16 + gid;

    {
        int r = tid >> 1;
        int sg = (tid & 1) * 4;
        const __half* qp = qkv + (size_t)(b*SEQ + q0 + r) * (3*DIM) + h*HDIM;
        #pragma unroll
        for (int j = 0; j < 4; j++) {
            uint4 w = ((const uint4*)qp)[sg + j];
            *(uint4*)&S[ASQ2 + r*36 + (sg + j)*4] = w;
        }
    }

    auto issue_tile = [&](int kt, int st) {
        int tokbase = b*SEQ + kt*64;
        #pragma unroll
        for (int i = 0; i < 2; i++) {
            int c   = tid + i*256;
            int row = c >> 3;
            int seg = c & 7;
            const __half* kg = qkv + (size_t)(tokbase + row) * (3*DIM) + DIM + h*HDIM + seg*8;
            CP_ASYNC16(smem_u32(&S[ASK2 + st*2304 + row*36 + seg*4]), kg);
            CP_ASYNC16(smem_u32(&S[ASV2 + st*2304 + row*36 + seg*4]), kg + DIM);
        }
        if (tid < 16) {
            CP_ASYNC16(smem_u32(&smk[st*64 + tid*4]), gm + tokbase + tid*4);
        }
    };

    issue_tile(0, 0);
    CP_COMMIT();

    int mq0 = gm[b*SEQ + q0 + qr];
    int mq1 = gm[b*SEQ + q0 + qr + 8];

    float m0 = -FLT_MAX, m1 = -FLT_MAX, l0 = 0.f, l1 = 0.f;
    float acc[8][4];
    #pragma unroll
    for (int nt = 0; nt < 8; nt++)
        acc[nt][0] = acc[nt][1] = acc[nt][2] = acc[nt][3] = 0.f;

    const uint32_t* q_u  = (const uint32_t*)(S + ASQ2);
    uint32_t*       p_u  = (uint32_t*)(S + ASP2);
    const uint32_t* vt_u = (const uint32_t*)(S + ASVT2);

    for (int kt = 0; kt < 16; kt++) {
        int s = kt & 1;
        CP_WAIT0();
        __syncthreads();

        if (kt < 15) { issue_tile(kt+1, s^1); CP_COMMIT(); }

        {
            int dp = tid & 31;
            int kp0 = tid >> 5;
            const __half2* vsrc = S + ASV2 + s*2304;
            #pragma unroll
            for (int j = 0; j < 4; j++) {
                int kp = kp0 + 8*j;
                __half2 v0 = vsrc[(2*kp)*36 + dp];
                __half2 v1 = vsrc[(2*kp+1)*36 + dp];
                S[ASVT2 + (2*dp)*36 + kp]   = __lows2half2(v0, v1);
                S[ASVT2 + (2*dp+1)*36 + kp] = __highs2half2(v0, v1);
            }
        }
        __syncthreads();

        float sc[8][4];
        #pragma unroll
        for (int nt = 0; nt < 8; nt++)
            sc[nt][0] = sc[nt][1] = sc[nt][2] = sc[nt][3] = 0.f;
        {
            const uint32_t* k_u = (const uint32_t*)(S + ASK2 + s*2304);
            #pragma unroll
            for (int ks = 0; ks < 4; ks++) {
                int k0 = 8*ks;
                uint32_t a0 = q_u[qr*36 + tig + k0];
                uint32_t a1 = q_u[(qr+8)*36 + tig + k0];
                uint32_t a2 = q_u[qr*36 + tig + 4 + k0];
                uint32_t a3 = q_u[(qr+8)*36 + tig + 4 + k0];
                #pragma unroll
                for (int nt = 0; nt < 8; nt++) {
                    uint32_t b0 = k_u[(8*nt+gid)*36 + tig + k0];
                    uint32_t b1 = k_u[(8*nt+gid)*36 + tig + 4 + k0];
                    mma_f16(sc[nt], a0, a1, a2, a3, b0, b1);
                }
            }
        }

        float mx0 = -FLT_MAX, mx1 = -FLT_MAX;
        #pragma unroll
        for (int nt = 0; nt < 8; nt++) {
            int kk = 8*nt + 2*tig;
            int ka_ = smk[s*64 + kk], kb_ = smk[s*64 + kk + 1];
            sc[nt][0] = (mq0 && ka_) ? sc[nt][0]*SCALE : -FLT_MAX;
            sc[nt][1] = (mq0 && kb_) ? sc[nt][1]*SCALE : -FLT_MAX;
            sc[nt][2] = (mq1 && ka_) ? sc[nt][2]*SCALE : -FLT_MAX;
            sc[nt][3] = (mq1 && kb_) ? sc[nt][3]*SCALE : -FLT_MAX;
            mx0 = fmaxf(mx0, fmaxf(sc[nt][0], sc[nt][1]));
            mx1 = fmaxf(mx1, fmaxf(sc[nt][2], sc[nt][3]));
        }
        mx0 = fmaxf(mx0, __shfl_xor_sync(0xffffffffu, mx0, 1));
        mx0 = fmaxf(mx0, __shfl_xor_sync(0xffffffffu, mx0, 2));
        mx1 = fmaxf(mx1, __shfl_xor_sync(0xffffffffu, mx1, 1));
        mx1 = fmaxf(mx1, __shfl_xor_sync(0xffffffffu, mx1, 2));

        float mn0 = fmaxf(m0, mx0), mn1 = fmaxf(m1, mx1);
        float c0 = __expf(m0 - mn0), c1 = __expf(m1 - mn1);
        float ps0 = 0.f, ps1 = 0.f;
        #pragma unroll
        for (int nt = 0; nt < 8; nt++) {
            float p00 = __expf(sc[nt][0] - mn0);
            float p01 = __expf(sc[nt][1] - mn0);
            float p10 = __expf(sc[nt][2] - mn1);
            float p11 = __expf(sc[nt][3] - mn1);
            ps0 += p00 + p01; ps1 += p10 + p11;
            int cp = 4*nt + tig;
            p_u[qr*36 + cp]     = h2_u32(__floats2half2_rn(p00, p01));
            p_u[(qr+8)*36 + cp] = h2_u32(__floats2half2_rn(p10, p11));
        }
        ps0 += __shfl_xor_sync(0xffffffffu, ps0, 1);
        ps0 += __shfl_xor_sync(0xffffffffu, ps0, 2);
        ps1 += __shfl_xor_sync(0xffffffffu, ps1, 1);
        ps1 += __shfl_xor_sync(0xffffffffu, ps1, 2);
        l0 = l0*c0 + ps0; l1 = l1*c1 + ps1;
        m0 = mn0; m1 = mn1;
        #pragma unroll
        for (int nt = 0; nt < 8; nt++) {
            acc[nt][0] *= c0; acc[nt][1] *= c0;
            acc[nt][2] *= c1; acc[nt][3] *= c1;
        }
        __syncwarp();

        #pragma unroll
        for (int ks = 0; ks < 4; ks++) {
            int k0 = 8*ks;
            uint32_t a0 = p_u[qr*36 + tig + k0];
            uint32_t a1 = p_u[(qr+8)*36 + tig + k0];
            uint32_t a2 = p_u[qr*36 + tig + 4 + k0];
            uint32_t a3 = p_u[(qr+8)*36 + tig + 4 + k0];
            #pragma unroll
            for (int nt = 0; nt < 8; nt++) {
                uint32_t b0 = vt_u[(8*nt+gid)*36 + tig + k0];
                uint32_t b1 = vt_u[(8*nt+gid)*36 + tig + 4 + k0];
                mma_f16(acc[nt], a0, a1, a2, a3, b0, b1);
            }
        }
    }

    float inv0 = 1.0f / l0, inv1 = 1.0f / l1;
    __half2* op0 = (__half2*)(outp + (size_t)(b*SEQ + q0 + qr) * DIM + h*HDIM);
    __half2* op1 = (__half2*)(outp + (size_t)(b*SEQ + q0 + qr + 8) * DIM + h*HDIM);
    #pragma unroll
    for (int nt = 0; nt < 8; nt++) {
        int cp = 4*nt + tig;
        op0[cp] = __floats2half2_rn(acc[nt][0]*inv0, acc[nt][1]*inv0);
        op1[cp] = __floats2half2_rn(acc[nt][2]*inv1, acc[nt][3]*inv1);
    }
}

// ======================= host side =======================
extern "C" void kernel_launch(void* const* d_in, const int* in_sizes, int n_in,
                              void* d_out, int out_size)
{
    const float* src   = (const float*)d_in[0];
    const unsigned char* maskraw = (const unsigned char*)d_in[1];
    const float* Wqkv  = (const float*)d_in[2];
    const float* Wproj = (const float*)d_in[3];
    const float* bproj = (const float*)d_in[4];
    const float* W1    = (const float*)d_in[5];
    const float* b1    = (const float*)d_in[6];
    const float* W2    = (const float*)d_in[7];
    const float* b2    = (const float*)d_in[8];
    const float* g0    = (const float*)d_in[9];
    const float* beta0 = (const float*)d_in[10];
    const float* g1    = (const float*)d_in[11];
    const float* beta1 = (const float*)d_in[12];
    float* out = (float*)d_out;

    __half *ln, *qkv, *att, *ffn, *wq, *wp, *w1c, *w2c;
    float *ln32, *x; int* msk;
    cudaGetSymbolAddress((void**)&ln,   g_ln);
    cudaGetSymbolAddress((void**)&ln32, g_ln32);
    cudaGetSymbolAddress((void**)&qkv,  g_qkv);
    cudaGetSymbolAddress((void**)&att,  g_att);
    cudaGetSymbolAddress((void**)&x,    g_x);
    cudaGetSymbolAddress((void**)&ffn,  g_ffn);
    cudaGetSymbolAddress((void**)&msk,  g_msk);
    cudaGetSymbolAddress((void**)&wq,   g_wq);
    cudaGetSymbolAddress((void**)&wp,   g_wp);
    cudaGetSymbolAddress((void**)&w1c,  g_w1);
    cudaGetSymbolAddress((void**)&w2c,  g_w2);

    cudaFuncSetAttribute(attn_mma, cudaFuncAttributeMaxDynamicSharedMemorySize, ATTN_BYTES);
    cudaFuncSetAttribute(gemm_mma<3*DIM, DIM,  false, false, false, true>,
                         cudaFuncAttributeMaxDynamicSharedMemorySize, GSMEM_BYTES);
    cudaFuncSetAttribute(gemm_mma<DIM,   DIM,  true,  false, true,  false>,
                         cudaFuncAttributeMaxDynamicSharedMemorySize, GSMEM_BYTES);
    cudaFuncSetAttribute(gemm_mma<FDIM,  DIM,  true,  true,  false, true>,
                         cudaFuncAttributeMaxDynamicSharedMemorySize, GSMEM_BYTES);
    cudaFuncSetAttribute(gemm_mma<DIM,   FDIM, true,  false, true,  false>,
                         cudaFuncAttributeMaxDynamicSharedMemorySize, GSMEM_BYTES);

    // 0. weights -> fp16 (one launch)
    {
        int n0 = 3*DIM*DIM/4, n1 = DIM*DIM/4, n2 = FDIM*DIM/4, n3 = DIM*FDIM/4;
        int ntot = n0 + n1 + n2 + n3;
        cvt_all_kernel<<<(ntot + 255)/256, 256>>>(
            (const float4*)Wqkv,  (__half2*)wq,  n0,
            (const float4*)Wproj, (__half2*)wp,  n1,
            (const float4*)W1,    (__half2*)w1c, n2,
            (const float4*)W2,    (__half2*)w2c, n3);
    }
    // 1. normalize mask
    mask_kernel<<<1, 256>>>(maskraw, msk);
    // 2. LN0 (half out)
    ln_kernel<false><<<TOK, 256>>>(src, g0, beta0, ln, nullptr);
    // 3. QKV projection -> half
    gemm_mma<3*DIM, DIM, false, false, false, true>
        <<<dim3(3*DIM/256, TOK/128), 256, GSMEM_BYTES>>>(ln, wq, nullptr, nullptr, qkv);
    // 4. attention (fp16 tensor-core flash, half out)
    attn_mma<<<dim3(SEQ/128, BATCH*NHEAD), 256, ATTN_BYTES>>>(qkv, msk, att);
    // 5. output projection + bias + residual(src) -> x (fp32)
    gemm_mma<DIM, DIM, true, false, true, false>
        <<<dim3(DIM/256, TOK/128), 256, GSMEM_BYTES>>>(att, wp, bproj, src, x);
    // 6. LN1 (half out + fp32 copy for FFN residual)
    ln_kernel<true><<<TOK, 256>>>(x, g1, beta1, ln, ln32);
    // 7. FFN1 + bias + exact GELU -> half
    gemm_mma<FDIM, DIM, true, true, false, true>
        <<<dim3(FDIM/256, TOK/128), 256, GSMEM_BYTES>>>(ln, w1c, b1, nullptr, ffn);
    // 8. FFN2 + bias + residual(LN1 fp32) -> out (fp32)
    gemm_mma<DIM, FDIM, true, false, true, false>
        <<<dim3(DIM/256, TOK/128), 256, GSMEM_BYTES>>>(ffn, w2c, b2, ln32, out);
}

// round 14
// speedup vs baseline: 1.0599x; 1.0599x over previous
#include <cuda_runtime.h>
#include <cuda_fp16.h>
#include <cfloat>
#include <math.h>
#include <stdint.h>

// Problem constants
#define BATCH 8
#define SEQ   1024
#define DIM   1024
#define NHEAD 16
#define HDIM  64
#define FDIM  4096
#define TOK   (BATCH*SEQ)   // 8192

// ---------------- scratch (static device globals; no allocation) ----------------
__device__ __half g_ln  [(size_t)TOK * DIM];    // LN out (half, feeds GEMM)
__device__ float  g_ln32[(size_t)TOK * DIM];    // LN1 fp32 copy (FFN2 residual)
__device__ __half g_qkv [(size_t)TOK * 3*DIM];  // qkv (half — feeds fp16 attention)
__device__ __half g_att [(size_t)TOK * DIM];    // attention out (half)
__device__ float  g_x   [(size_t)TOK * DIM];    // src + proj(att) (fp32)
__device__ __half g_ffn [(size_t)TOK * FDIM];   // GELU(FFN1) (half)
__device__ int    g_msk [TOK];
// half weight copies
__device__ __half g_wq[(size_t)3*DIM*DIM];
__device__ __half g_wp[(size_t)DIM*DIM];
__device__ __half g_w1[(size_t)FDIM*DIM];
__device__ __half g_w2[(size_t)DIM*FDIM];

// ======================= small helpers =======================
__device__ __forceinline__ uint32_t smem_u32(const void* p) {
    uint32_t a;
    asm("{ .reg .u64 t; cvta.to.shared.u64 t, %1; cvt.u32.u64 %0, t; }" : "=r"(a) : "l"(p));
    return a;
}

__device__ __forceinline__ uint32_t h2_u32(__half2 h) {
    uint32_t u;
    memcpy(&u, &h, 4);
    return u;
}

__device__ __forceinline__ void mma_f16(float c[4],
                                        uint32_t a0, uint32_t a1, uint32_t a2, uint32_t a3,
                                        uint32_t b0, uint32_t b1) {
    asm volatile(
        "mma.sync.aligned.m16n8k16.row.col.f32.f16.f16.f32 "
        "{%0,%1,%2,%3}, {%4,%5,%6,%7}, {%8,%9}, {%0,%1,%2,%3};"
        : "+f"(c[0]), "+f"(c[1]), "+f"(c[2]), "+f"(c[3])
        : "r"(a0), "r"(a1), "r"(a2), "r"(a3), "r"(b0), "r"(b1));
}

#define LDSM_X4(r0, r1, r2, r3, addr) \
    asm volatile("ldmatrix.sync.aligned.m8n8.x4.shared.b16 {%0,%1,%2,%3}, [%4];" \
        : "=r"(r0), "=r"(r1), "=r"(r2), "=r"(r3) : "r"(addr))

#define CP_ASYNC16(saddr, gptr) \
    asm volatile("cp.async.cg.shared.global [%0], [%1], 16;" :: "r"(saddr), "l"(gptr))
#define CP_COMMIT() asm volatile("cp.async.commit_group;")
#define CP_WAIT1()  asm volatile("cp.async.wait_group 1;")
#define CP_WAIT0()  asm volatile("cp.async.wait_group 0;")

__device__ __forceinline__ float gelu_f(float x)
{
    return 0.5f * x * (1.0f + erff(x * 0.70710678118654752f));
}

// ---------------- fp32 -> fp16 conversion of ALL weights in one launch ----------------
__global__ void cvt_all_kernel(const float4* __restrict__ i0, __half2* __restrict__ o0, int n0,
                               const float4* __restrict__ i1, __half2* __restrict__ o1, int n1,
                               const float4* __restrict__ i2, __half2* __restrict__ o2, int n2,
                               const float4* __restrict__ i3, __half2* __restrict__ o3, int n3)
{
    int idx = blockIdx.x * blockDim.x + threadIdx.x;
    const float4* in; __half2* out;
    if (idx < n0)              { in = i0; out = o0; }
    else if ((idx -= n0) < n1) { in = i1; out = o1; }
    else if ((idx -= n1) < n2) { in = i2; out = o2; }
    else if ((idx -= n2) < n3) { in = i3; out = o3; }
    else return;
    float4 v = in[idx];
    out[2*idx]   = __floats2half2_rn(v.x, v.y);
    out[2*idx+1] = __floats2half2_rn(v.z, v.w);
}

// ---------------- mask dtype detection + normalization ----------------
__global__ void mask_kernel(const unsigned char* __restrict__ raw, int* __restrict__ gm)
{
    __shared__ int cnt[4];
    int t = threadIdx.x;
    if (t < 4) cnt[t] = 0;
    __syncthreads();
    int l1=0, l2=0, l3=0, lb=0;
    for (int i = t; i < TOK; i += blockDim.x) {
        unsigned char bch = raw[i];
        if (bch) {
            int m = i & 3;
            if (m == 1) l1++;
            else if (m == 2) l2++;
            else if (m == 3) l3++;
            if (bch > 1) lb++;
        }
    }
    atomicAdd(&cnt[0], l1); atomicAdd(&cnt[1], l2);
    atomicAdd(&cnt[2], l3); atomicAdd(&cnt[3], lb);
    __syncthreads();
    int c1 = cnt[0], c2 = cnt[1], c3 = cnt[2], cb = cnt[3];
    int type;
    if (c1 < 64 && c2 < 64 && c3 < 64) type = 0;
    else if (c1 < 64)                  type = 1;
    else if (cb < 64)                  type = 2;
    else                               type = 3;
    for (int i = t; i < TOK; i += blockDim.x) {
        int v;
        if      (type == 0) v = (((const int*)raw)[i] != 0);
        else if (type == 1) v = (((const float*)raw)[i] != 0.0f);
        else if (type == 2) v = (raw[i] != 0);
        else                v = (((const unsigned short*)raw)[i] != 0);
        gm[i] = v;
    }
}

// ---------------- LayerNorm: half out (+ optional fp32 copy) ----------------
template<bool WF>
__global__ void ln_kernel(const float* __restrict__ in,
                          const float* __restrict__ gamma,
                          const float* __restrict__ beta,
                          __half* __restrict__ outh,
                          float* __restrict__ outf)
{
    int row = blockIdx.x;
    int t = threadIdx.x;
    const float* xr = in + (size_t)row * DIM;
    float4 v = ((const float4*)xr)[t];
    float s = v.x + v.y + v.z + v.w;
    float q = v.x*v.x + v.y*v.y + v.z*v.z + v.w*v.w;
    #pragma unroll
    for (int o = 16; o; o >>= 1) {
        s += __shfl_xor_sync(0xffffffffu, s, o);
        q += __shfl_xor_sync(0xffffffffu, q, o);
    }
    __shared__ float ss[8], qq[8];
    if ((t & 31) == 0) { ss[t >> 5] = s; qq[t >> 5] = q; }
    __syncthreads();
    s = 0.f; q = 0.f;
    #pragma unroll
    for (int i = 0; i < 8; i++) { s += ss[i]; q += qq[i]; }
    float mean = s * (1.0f / DIM);
    float var  = q * (1.0f / DIM) - mean * mean;
    float rstd = rsqrtf(var + 1e-5f);
    float4 gv = ((const float4*)gamma)[t];
    float4 bv = ((const float4*)beta)[t];
    float ox = (v.x - mean) * rstd * gv.x + bv.x;
    float oy = (v.y - mean) * rstd * gv.y + bv.y;
    float oz = (v.z - mean) * rstd * gv.z + bv.z;
    float ow = (v.w - mean) * rstd * gv.w + bv.w;
    __half2* oh = (__half2*)(outh + (size_t)row * DIM);
    oh[2*t]   = __floats2half2_rn(ox, oy);
    oh[2*t+1] = __floats2half2_rn(oz, ow);
    if (WF) {
        float4 o = {ox, oy, oz, ow};
        ((float4*)(outf + (size_t)row * DIM))[t] = o;
    }
}

// ======================= FP16 mma.sync GEMM — 128x128 tile, 4 warps, warp 64x64 =======================
// C[M,N] = A[M,K] @ B[N,K]^T (+bias/gelu/res). 128 threads (2x2 warp grid), 2-stage
// pipeline (proven R11 sync structure), ldmatrix fragments, row stride 20 half2 (80B).
// SMEM: [A s0 | A s1 | B s0 | B s1] = 40960 B -> 2 CTAs/SM.
#define SH2 20
#define HSTG (128*SH2)                    // half2 per matrix per stage (2560)
#define HSTG_B (HSTG*4)                   // stage stride in bytes (10240)
#define GSMEM_BYTES (4*HSTG*4)            // 40960

template<int N, int K, bool HAS_BIAS, bool HAS_GELU, bool HAS_RES, bool OUT_HALF>
__global__ void __launch_bounds__(128, 2)
gemm_mma(const __half* __restrict__ A, const __half* __restrict__ Bm,
         const float* __restrict__ bias, const float* __restrict__ res,
         void* __restrict__ Cout)
{
    extern __shared__ __half2 sh[];
    __half2* As0 = sh;                    // A stages 0,1
    __half2* Bs0 = sh + 2*HSTG;           // B stages 0,1

    int tid  = threadIdx.x;
    int lane = tid & 31, warp = tid >> 5;   // warp 0..3
    int wm = warp >> 1, wn = warp & 1;      // 2x2 warp grid
    int gid = lane >> 2, tig = lane & 3;
    int bm = blockIdx.y * 128, bn = blockIdx.x * 128;

    // loader: 128 rows x 4 segs (16B) per matrix = 512 chunks, 4 per thread
    // rows (tid>>2) + 32*i, seg = tid&3
    int lrow = tid >> 2;          // 0..31
    int lseg = tid & 3;           // 0..3
    const __half* gA = A  + (size_t)(bm + lrow) * K + lseg * 8;
    const __half* gB = Bm + (size_t)(bn + lrow) * K + lseg * 8;
    uint32_t uA = smem_u32(&As0[lrow*SH2 + lseg*4]);
    uint32_t uB = smem_u32(&Bs0[lrow*SH2 + lseg*4]);
    const uint32_t SROW32 = 32u * SH2 * 4u;
    const size_t  GROW32 = (size_t)32 * K;

    // ldmatrix per-lane addresses (stage 0 base)
    int lane15 = lane & 15;
    int lq     = lane >> 4;
    uint32_t aAddr[4];
    #pragma unroll
    for (int mt = 0; mt < 4; mt++)
        aAddr[mt] = smem_u32(&As0[(wm*64 + mt*16 + lane15)*SH2]) + lq*16;
    uint32_t bAddr[4];
    {
        int quad = lane >> 3;
        int l7   = lane & 7;
        #pragma unroll
        for (int p = 0; p < 4; p++) {
            int row = wn*64 + (2*p + (quad >> 1))*8 + l7;
            bAddr[p] = smem_u32(&Bs0[row*SH2]) + (quad & 1)*16;
        }
    }

    float acc[4][8][4];
    #pragma unroll
    for (int mt = 0; mt < 4; mt++)
        #pragma unroll
        for (int nt = 0; nt < 8; nt++)
            #pragma unroll
            for (int e = 0; e < 4; e++) acc[mt][nt][e] = 0.f;

    const int KT = K / 32;

    // prefetch stage 0
    #pragma unroll
    for (int i = 0; i < 4; i++) {
        CP_ASYNC16(uA + i*SROW32, gA + i*GROW32);
        CP_ASYNC16(uB + i*SROW32, gB + i*GROW32);
    }
    CP_COMMIT();

    for (int kt = 0; kt < KT; kt++) {
        int cur = kt & 1;
        if (kt + 1 < KT) {
            int nxt = cur ^ 1;
            size_t go = (size_t)(kt + 1) * 32;
            uint32_t so = (uint32_t)nxt * HSTG_B;
            #pragma unroll
            for (int i = 0; i < 4; i++) {
                CP_ASYNC16(uA + so + i*SROW32, gA + go + i*GROW32);
                CP_ASYNC16(uB + so + i*SROW32, gB + go + i*GROW32);
            }
            CP_COMMIT();
            CP_WAIT1();
        } else {
            CP_WAIT0();
        }
        __syncthreads();

        uint32_t stoff = (uint32_t)cur * HSTG_B;
        #pragma unroll
        for (int ks = 0; ks < 2; ks++) {
            uint32_t ko = ks * 32;
            uint32_t af[4][4];
            #pragma unroll
            for (int mt = 0; mt < 4; mt++)
                LDSM_X4(af[mt][0], af[mt][1], af[mt][2], af[mt][3],
                        aAddr[mt] + stoff + ko);
            #pragma unroll
            for (int p = 0; p < 4; p++) {
                uint32_t b0, b1, b2, b3;
                LDSM_X4(b0, b1, b2, b3, bAddr[p] + stoff + ko);
                #pragma unroll
                for (int mt = 0; mt < 4; mt++) {
                    mma_f16(acc[mt][2*p],   af[mt][0], af[mt][1], af[mt][2], af[mt][3], b0, b1);
                    mma_f16(acc[mt][2*p+1], af[mt][0], af[mt][1], af[mt][2], af[mt][3], b2, b3);
                }
            }
        }
        __syncthreads();
    }

    #pragma unroll
    for (int mt = 0; mt < 4; mt++) {
        int row = bm + wm*64 + mt*16 + gid;
        #pragma unroll
        for (int nt = 0; nt < 8; nt++) {
            int col = bn + wn*64 + nt*8 + 2*tig;
            float2 bb = {0.f, 0.f};
            if (HAS_BIAS) bb = *(const float2*)&bias[col];
            #pragma unroll
            for (int half_ = 0; half_ < 2; half_++) {
                int rr = row + half_*8;
                float vx = acc[mt][nt][half_*2+0];
                float vy = acc[mt][nt][half_*2+1];
                if (HAS_BIAS) { vx += bb.x; vy += bb.y; }
                if (HAS_GELU) { vx = gelu_f(vx); vy = gelu_f(vy); }
                if (HAS_RES) {
                    float2 rv = *(const float2*)&res[(size_t)rr * N + col];
                    vx += rv.x; vy += rv.y;
                }
                if (OUT_HALF) {
                    __half2* cp = (__half2*)((__half*)Cout + (size_t)rr * N + col);
                    *cp = __floats2half2_rn(vx, vy);
                } else {
                    float2 o2 = {vx, vy};
                    *(float2*)((float*)Cout + (size_t)rr * N + col) = o2;
                }
            }
        }
    }
}

// ======================= fp16 flash attention (proven in R11) =======================
#define ASQ2  0
#define ASK2  4608
#define ASV2  9216
#define ASVT2 13824
#define ASP2  16128
#define AH2TOT 20736
#define ATTN_BYTES (AH2TOT*4 + 2*64*4)   // 83456

__global__ void __launch_bounds__(256)
attn_mma(const __half* __restrict__ qkv, const int* __restrict__ gm,
         __half* __restrict__ outp)
{
    extern __shared__ __half2 S[];
    int* smk = (int*)(S + AH2TOT);

    const float SCALE = 0.125f;
    int tid = threadIdx.x, lane = tid & 31, warp = tid >> 5;
    int gid = lane >> 2, tig = lane & 3;
    int bh = blockIdx.y, b = bh >> 4, h = bh & 15;
    int q0 = blockIdx.x * 128;
    int qr = warp*16 + gid;

    {
        int r = tid >> 1;
        int sg = (tid & 1) * 4;
        const __half* qp = qkv + (size_t)(b*SEQ + q0 + r) * (3*DIM) + h*HDIM;
        #pragma unroll
        for (int j = 0; j < 4; j++) {
            uint4 w = ((const uint4*)qp)[sg + j];
            *(uint4*)&S[ASQ2 + r*36 + (sg + j)*4] = w;
        }
    }

    auto issue_tile = [&](int kt, int st) {
        int tokbase = b*SEQ + kt*64;
        #pragma unroll
        for (int i = 0; i < 2; i++) {
            int c   = tid + i*256;
            int row = c >> 3;
            int seg = c & 7;
            const __half* kg = qkv + (size_t)(tokbase + row) * (3*DIM) + DIM + h*HDIM + seg*8;
            CP_ASYNC16(smem_u32(&S[ASK2 + st*2304 + row*36 + seg*4]), kg);
            CP_ASYNC16(smem_u32(&S[ASV2 + st*2304 + row*36 + seg*4]), kg + DIM);
        }
        if (tid < 16) {
            CP_ASYNC16(smem_u32(&smk[st*64 + tid*4]), gm + tokbase + tid*4);
        }
    };

    issue_tile(0, 0);
    CP_COMMIT();

    int mq0 = gm[b*SEQ + q0 + qr];
    int mq1 = gm[b*SEQ + q0 + qr + 8];

    float m0 = -FLT_MAX, m1 = -FLT_MAX, l0 = 0.f, l1 = 0.f;
    float acc[8][4];
    #pragma unroll
    for (int nt = 0; nt < 8; nt++)
        acc[nt][0] = acc[nt][1] = acc[nt][2] = acc[nt][3] = 0.f;

    const uint32_t* q_u  = (const uint32_t*)(S + ASQ2);
    uint32_t*       p_u  = (uint32_t*)(S + ASP2);
    const uint32_t* vt_u = (const uint32_t*)(S + ASVT2);

    for (int kt = 0; kt < 16; kt++) {
        int s = kt & 1;
        CP_WAIT0();
        __syncthreads();

        if (kt < 15) { issue_tile(kt+1, s^1); CP_COMMIT(); }

        {
            int dp = tid & 31;
            int kp0 = tid >> 5;
            const __half2* vsrc = S + ASV2 + s*2304;
            #pragma unroll
            for (int j = 0; j < 4; j++) {
                int kp = kp0 + 8*j;
                __half2 v0 = vsrc[(2*kp)*36 + dp];
                __half2 v1 = vsrc[(2*kp+1)*36 + dp];
                S[ASVT2 + (2*dp)*36 + kp]   = __lows2half2(v0, v1);
                S[ASVT2 + (2*dp+1)*36 + kp] = __highs2half2(v0, v1);
            }
        }
        __syncthreads();

        float sc[8][4];
        #pragma unroll
        for (int nt = 0; nt < 8; nt++)
            sc[nt][0] = sc[nt][1] = sc[nt][2] = sc[nt][3] = 0.f;
        {
            const uint32_t* k_u = (const uint32_t*)(S + ASK2 + s*2304);
            #pragma unroll
            for (int ks = 0; ks < 4; ks++) {
                int k0 = 8*ks;
                uint32_t a0 = q_u[qr*36 + tig + k0];
                uint32_t a1 = q_u[(qr+8)*36 + tig + k0];
                uint32_t a2 = q_u[qr*36 + tig + 4 + k0];
                uint32_t a3 = q_u[(qr+8)*36 + tig + 4 + k0];
                #pragma unroll
                for (int nt = 0; nt < 8; nt++) {
                    uint32_t b0 = k_u[(8*nt+gid)*36 + tig + k0];
                    uint32_t b1 = k_u[(8*nt+gid)*36 + tig + 4 + k0];
                    mma_f16(sc[nt], a0, a1, a2, a3, b0, b1);
                }
            }
        }

        float mx0 = -FLT_MAX, mx1 = -FLT_MAX;
        #pragma unroll
        for (int nt = 0; nt < 8; nt++) {
            int kk = 8*nt + 2*tig;
            int ka_ = smk[s*64 + kk], kb_ = smk[s*64 + kk + 1];
            sc[nt][0] = (mq0 && ka_) ? sc[nt][0]*SCALE : -FLT_MAX;
            sc[nt][1] = (mq0 && kb_) ? sc[nt][1]*SCALE : -FLT_MAX;
            sc[nt][2] = (mq1 && ka_) ? sc[nt][2]*SCALE : -FLT_MAX;
            sc[nt][3] = (mq1 && kb_) ? sc[nt][3]*SCALE : -FLT_MAX;
            mx0 = fmaxf(mx0, fmaxf(sc[nt][0], sc[nt][1]));
            mx1 = fmaxf(mx1, fmaxf(sc[nt][2], sc[nt][3]));
        }
        mx0 = fmaxf(mx0, __shfl_xor_sync(0xffffffffu, mx0, 1));
        mx0 = fmaxf(mx0, __shfl_xor_sync(0xffffffffu, mx0, 2));
        mx1 = fmaxf(mx1, __shfl_xor_sync(0xffffffffu, mx1, 1));
        mx1 = fmaxf(mx1, __shfl_xor_sync(0xffffffffu, mx1, 2));

        float mn0 = fmaxf(m0, mx0), mn1 = fmaxf(m1, mx1);
        float c0 = __expf(m0 - mn0), c1 = __expf(m1 - mn1);
        float ps0 = 0.f, ps1 = 0.f;
        #pragma unroll
        for (int nt = 0; nt < 8; nt++) {
            float p00 = __expf(sc[nt][0] - mn0);
            float p01 = __expf(sc[nt][1] - mn0);
            float p10 = __expf(sc[nt][2] - mn1);
            float p11 = __expf(sc[nt][3] - mn1);
            ps0 += p00 + p01; ps1 += p10 + p11;
            int cp = 4*nt + tig;
            p_u[qr*36 + cp]     = h2_u32(__floats2half2_rn(p00, p01));
            p_u[(qr+8)*36 + cp] = h2_u32(__floats2half2_rn(p10, p11));
        }
        ps0 += __shfl_xor_sync(0xffffffffu, ps0, 1);
        ps0 += __shfl_xor_sync(0xffffffffu, ps0, 2);
        ps1 += __shfl_xor_sync(0xffffffffu, ps1, 1);
        ps1 += __shfl_xor_sync(0xffffffffu, ps1, 2);
        l0 = l0*c0 + ps0; l1 = l1*c1 + ps1;
        m0 = mn0; m1 = mn1;
        #pragma unroll
        for (int nt = 0; nt < 8; nt++) {
            acc[nt][0] *= c0; acc[nt][1] *= c0;
            acc[nt][2] *= c1; acc[nt][3] *= c1;
        }
        __syncwarp();

        #pragma unroll
        for (int ks = 0; ks < 4; ks++) {
            int k0 = 8*ks;
            uint32_t a0 = p_u[qr*36 + tig + k0];
            uint32_t a1 = p_u[(qr+8)*36 + tig + k0];
            uint32_t a2 = p_u[qr*36 + tig + 4 + k0];
            uint32_t a3 = p_u[(qr+8)*36 + tig + 4 + k0];
            #pragma unroll
            for (int nt = 0; nt < 8; nt++) {
                uint32_t b0 = vt_u[(8*nt+gid)*36 + tig + k0];
                uint32_t b1 = vt_u[(8*nt+gid)*36 + tig + 4 + k0];
                mma_f16(acc[nt], a0, a1, a2, a3, b0, b1);
            }
        }
    }

    float inv0 = 1.0f / l0, inv1 = 1.0f / l1;
    __half2* op0 = (__half2*)(outp + (size_t)(b*SEQ + q0 + qr) * DIM + h*HDIM);
    __half2* op1 = (__half2*)(outp + (size_t)(b*SEQ + q0 + qr + 8) * DIM + h*HDIM);
    #pragma unroll
    for (int nt = 0; nt < 8; nt++) {
        int cp = 4*nt + tig;
        op0[cp] = __floats2half2_rn(acc[nt][0]*inv0, acc[nt][1]*inv0);
        op1[cp] = __floats2half2_rn(acc[nt][2]*inv1, acc[nt][3]*inv1);
    }
}

// ======================= host side =======================
extern "C" void kernel_launch(void* const* d_in, const int* in_sizes, int n_in,
                              void* d_out, int out_size)
{
    const float* src   = (const float*)d_in[0];
    const unsigned char* maskraw = (const unsigned char*)d_in[1];
    const float* Wqkv  = (const float*)d_in[2];
    const float* Wproj = (const float*)d_in[3];
    const float* bproj = (const float*)d_in[4];
    const float* W1    = (const float*)d_in[5];
    const float* b1    = (const float*)d_in[6];
    const float* W2    = (const float*)d_in[7];
    const float* b2    = (const float*)d_in[8];
    const float* g0    = (const float*)d_in[9];
    const float* beta0 = (const float*)d_in[10];
    const float* g1    = (const float*)d_in[11];
    const float* beta1 = (const float*)d_in[12];
    float* out = (float*)d_out;

    __half *ln, *qkv, *att, *ffn, *wq, *wp, *w1c, *w2c;
    float *ln32, *x; int* msk;
    cudaGetSymbolAddress((void**)&ln,   g_ln);
    cudaGetSymbolAddress((void**)&ln32, g_ln32);
    cudaGetSymbolAddress((void**)&qkv,  g_qkv);
    cudaGetSymbolAddress((void**)&att,  g_att);
    cudaGetSymbolAddress((void**)&x,    g_x);
    cudaGetSymbolAddress((void**)&ffn,  g_ffn);
    cudaGetSymbolAddress((void**)&msk,  g_msk);
    cudaGetSymbolAddress((void**)&wq,   g_wq);
    cudaGetSymbolAddress((void**)&wp,   g_wp);
    cudaGetSymbolAddress((void**)&w1c,  g_w1);
    cudaGetSymbolAddress((void**)&w2c,  g_w2);

    cudaFuncSetAttribute(attn_mma, cudaFuncAttributeMaxDynamicSharedMemorySize, ATTN_BYTES);

    // 0. weights -> fp16 (one launch)
    {
        int n0 = 3*DIM*DIM/4, n1 = DIM*DIM/4, n2 = FDIM*DIM/4, n3 = DIM*FDIM/4;
        int ntot = n0 + n1 + n2 + n3;
        cvt_all_kernel<<<(ntot + 255)/256, 256>>>(
            (const float4*)Wqkv,  (__half2*)wq,  n0,
            (const float4*)Wproj, (__half2*)wp,  n1,
            (const float4*)W1,    (__half2*)w1c, n2,
            (const float4*)W2,    (__half2*)w2c, n3);
    }
    // 1. normalize mask
    mask_kernel<<<1, 256>>>(maskraw, msk);
    // 2. LN0 (half out)
    ln_kernel<false><<<TOK, 256>>>(src, g0, beta0, ln, nullptr);
    // 3. QKV projection -> half
    gemm_mma<3*DIM, DIM, false, false, false, true>
        <<<dim3(3*DIM/128, TOK/128), 128, GSMEM_BYTES>>>(ln, wq, nullptr, nullptr, qkv);
    // 4. attention (fp16 tensor-core flash, half out)
    attn_mma<<<dim3(SEQ/128, BATCH*NHEAD), 256, ATTN_BYTES>>>(qkv, msk, att);
    // 5. output projection + bias + residual(src) -> x (fp32)
    gemm_mma<DIM, DIM, true, false, true, false>
        <<<dim3(DIM/128, TOK/128), 128, GSMEM_BYTES>>>(att, wp, bproj, src, x);
    // 6. LN1 (half out + fp32 copy for FFN residual)
    ln_kernel<true><<<TOK, 256>>>(x, g1, beta1, ln, ln32);
    // 7. FFN1 + bias + exact GELU -> half
    gemm_mma<FDIM, DIM, true, true, false, true>
        <<<dim3(FDIM/128, TOK/128), 128, GSMEM_BYTES>>>(ln, w1c, b1, nullptr, ffn);
    // 8. FFN2 + bias + residual(LN1 fp32) -> out (fp32)
    gemm_mma<DIM, FDIM, true, false, true, false>
        <<<dim3(DIM/128, TOK/128), 128, GSMEM_BYTES>>>(ffn, w2c, b2, ln32, out);
}

// round 15
// speedup vs baseline: 1.1591x; 1.0936x over previous
#include <cuda_runtime.h>
#include <cuda_fp16.h>
#include <cfloat>
#include <math.h>
#include <stdint.h>

// Problem constants
#define BATCH 8
#define SEQ   1024
#define DIM   1024
#define NHEAD 16
#define HDIM  64
#define FDIM  4096
#define TOK   (BATCH*SEQ)   // 8192

// ---------------- scratch (static device globals; no allocation) ----------------
__device__ __half g_ln  [(size_t)TOK * DIM];    // LN out (half, feeds GEMM)
__device__ float  g_ln32[(size_t)TOK * DIM];    // LN1 fp32 copy (FFN2 residual)
__device__ __half g_qkv [(size_t)TOK * 3*DIM];  // qkv (half — feeds fp16 attention)
__device__ __half g_att [(size_t)TOK * DIM];    // attention out (half)
__device__ float  g_x   [(size_t)TOK * DIM];    // src + proj(att) (fp32)
__device__ __half g_ffn [(size_t)TOK * FDIM];   // GELU(FFN1) (half)
__device__ int    g_msk [TOK];
// half weight copies
__device__ __half g_wq[(size_t)3*DIM*DIM];
__device__ __half g_wp[(size_t)DIM*DIM];
__device__ __half g_w1[(size_t)FDIM*DIM];
__device__ __half g_w2[(size_t)DIM*FDIM];

// ======================= small helpers =======================
__device__ __forceinline__ uint32_t smem_u32(const void* p) {
    uint32_t a;
    asm("{ .reg .u64 t; cvta.to.shared.u64 t, %1; cvt.u32.u64 %0, t; }" : "=r"(a) : "l"(p));
    return a;
}

__device__ __forceinline__ uint32_t h2_u32(__half2 h) {
    uint32_t u;
    memcpy(&u, &h, 4);
    return u;
}

__device__ __forceinline__ void mma_f16(float c[4],
                                        uint32_t a0, uint32_t a1, uint32_t a2, uint32_t a3,
                                        uint32_t b0, uint32_t b1) {
    asm volatile(
        "mma.sync.aligned.m16n8k16.row.col.f32.f16.f16.f32 "
        "{%0,%1,%2,%3}, {%4,%5,%6,%7}, {%8,%9}, {%0,%1,%2,%3};"
        : "+f"(c[0]), "+f"(c[1]), "+f"(c[2]), "+f"(c[3])
        : "r"(a0), "r"(a1), "r"(a2), "r"(a3), "r"(b0), "r"(b1));
}

#define LDSM_X4(r0, r1, r2, r3, addr) \
    asm volatile("ldmatrix.sync.aligned.m8n8.x4.shared.b16 {%0,%1,%2,%3}, [%4];" \
        : "=r"(r0), "=r"(r1), "=r"(r2), "=r"(r3) : "r"(addr))

#define CP_ASYNC16(saddr, gptr) \
    asm volatile("cp.async.cg.shared.global [%0], [%1], 16;" :: "r"(saddr), "l"(gptr))
#define CP_COMMIT() asm volatile("cp.async.commit_group;")
#define CP_WAIT1()  asm volatile("cp.async.wait_group 1;")
#define CP_WAIT0()  asm volatile("cp.async.wait_group 0;")

__device__ __forceinline__ float gelu_f(float x)
{
    return 0.5f * x * (1.0f + erff(x * 0.70710678118654752f));
}

// ---------------- fp32 -> fp16 conversion of ALL weights in one launch ----------------
__global__ void cvt_all_kernel(const float4* __restrict__ i0, __half2* __restrict__ o0, int n0,
                               const float4* __restrict__ i1, __half2* __restrict__ o1, int n1,
                               const float4* __restrict__ i2, __half2* __restrict__ o2, int n2,
                               const float4* __restrict__ i3, __half2* __restrict__ o3, int n3)
{
    int idx = blockIdx.x * blockDim.x + threadIdx.x;
    const float4* in; __half2* out;
    if (idx < n0)              { in = i0; out = o0; }
    else if ((idx -= n0) < n1) { in = i1; out = o1; }
    else if ((idx -= n1) < n2) { in = i2; out = o2; }
    else if ((idx -= n2) < n3) { in = i3; out = o3; }
    else return;
    float4 v = in[idx];
    out[2*idx]   = __floats2half2_rn(v.x, v.y);
    out[2*idx+1] = __floats2half2_rn(v.z, v.w);
}

// ---------------- mask dtype detection + normalization ----------------
__global__ void mask_kernel(const unsigned char* __restrict__ raw, int* __restrict__ gm)
{
    __shared__ int cnt[4];
    int t = threadIdx.x;
    if (t < 4) cnt[t] = 0;
    __syncthreads();
    int l1=0, l2=0, l3=0, lb=0;
    for (int i = t; i < TOK; i += blockDim.x) {
        unsigned char bch = raw[i];
        if (bch) {
            int m = i & 3;
            if (m == 1) l1++;
            else if (m == 2) l2++;
            else if (m == 3) l3++;
            if (bch > 1) lb++;
        }
    }
    atomicAdd(&cnt[0], l1); atomicAdd(&cnt[1], l2);
    atomicAdd(&cnt[2], l3); atomicAdd(&cnt[3], lb);
    __syncthreads();
    int c1 = cnt[0], c2 = cnt[1], c3 = cnt[2], cb = cnt[3];
    int type;
    if (c1 < 64 && c2 < 64 && c3 < 64) type = 0;
    else if (c1 < 64)                  type = 1;
    else if (cb < 64)                  type = 2;
    else                               type = 3;
    for (int i = t; i < TOK; i += blockDim.x) {
        int v;
        if      (type == 0) v = (((const int*)raw)[i] != 0);
        else if (type == 1) v = (((const float*)raw)[i] != 0.0f);
        else if (type == 2) v = (raw[i] != 0);
        else                v = (((const unsigned short*)raw)[i] != 0);
        gm[i] = v;
    }
}

// ---------------- LayerNorm: half out (+ optional fp32 copy) ----------------
template<bool WF>
__global__ void ln_kernel(const float* __restrict__ in,
                          const float* __restrict__ gamma,
                          const float* __restrict__ beta,
                          __half* __restrict__ outh,
                          float* __restrict__ outf)
{
    int row = blockIdx.x;
    int t = threadIdx.x;
    const float* xr = in + (size_t)row * DIM;
    float4 v = ((const float4*)xr)[t];
    float s = v.x + v.y + v.z + v.w;
    float q = v.x*v.x + v.y*v.y + v.z*v.z + v.w*v.w;
    #pragma unroll
    for (int o = 16; o; o >>= 1) {
        s += __shfl_xor_sync(0xffffffffu, s, o);
        q += __shfl_xor_sync(0xffffffffu, q, o);
    }
    __shared__ float ss[8], qq[8];
    if ((t & 31) == 0) { ss[t >> 5] = s; qq[t >> 5] = q; }
    __syncthreads();
    s = 0.f; q = 0.f;
    #pragma unroll
    for (int i = 0; i < 8; i++) { s += ss[i]; q += qq[i]; }
    float mean = s * (1.0f / DIM);
    float var  = q * (1.0f / DIM) - mean * mean;
    float rstd = rsqrtf(var + 1e-5f);
    float4 gv = ((const float4*)gamma)[t];
    float4 bv = ((const float4*)beta)[t];
    float ox = (v.x - mean) * rstd * gv.x + bv.x;
    float oy = (v.y - mean) * rstd * gv.y + bv.y;
    float oz = (v.z - mean) * rstd * gv.z + bv.z;
    float ow = (v.w - mean) * rstd * gv.w + bv.w;
    __half2* oh = (__half2*)(outh + (size_t)row * DIM);
    oh[2*t]   = __floats2half2_rn(ox, oy);
    oh[2*t+1] = __floats2half2_rn(oz, ow);
    if (WF) {
        float4 o = {ox, oy, oz, ow};
        ((float4*)(outf + (size_t)row * DIM))[t] = o;
    }
}

// ======================= FP16 mma.sync GEMM (byte-exact R11 winner) =======================
#define SH2 20
#define HSTG (128*SH2)                    // half2 per matrix per stage (2560)
#define HSTG_B (HSTG*4)                   // stage stride in bytes (10240)
#define GSMEM_BYTES (4*HSTG*4)            // 40960

template<int N, int K, bool HAS_BIAS, bool HAS_GELU, bool HAS_RES, bool OUT_HALF>
__global__ void __launch_bounds__(256, 2)
gemm_mma(const __half* __restrict__ A, const __half* __restrict__ Bm,
         const float* __restrict__ bias, const float* __restrict__ res,
         void* __restrict__ Cout)
{
    extern __shared__ __half2 sh[];
    __half2* As0 = sh;
    __half2* Bs0 = sh + 2*HSTG;

    int tid  = threadIdx.x;
    int lane = tid & 31, warp = tid >> 5;
    int wm = warp >> 2, wn = warp & 3;
    int gid = lane >> 2, tig = lane & 3;
    int bm = blockIdx.y * 128, bn = blockIdx.x * 128;

    int lrow = tid >> 2;          // 0..63
    int lseg = tid & 3;           // 0..3
    const __half* gA = A  + (size_t)(bm + lrow) * K + lseg * 8;
    const __half* gB = Bm + (size_t)(bn + lrow) * K + lseg * 8;
    uint32_t sA[2], sB[2];
    #pragma unroll
    for (int st = 0; st < 2; st++) {
        sA[st] = smem_u32(&As0[st*HSTG + lrow*SH2 + lseg*4]);
        sB[st] = smem_u32(&Bs0[st*HSTG + lrow*SH2 + lseg*4]);
    }
    const uint32_t SROW64 = 64u * SH2 * 4u;
    const size_t  GROW64 = (size_t)64 * K;

    int lane15 = lane & 15;
    int lq     = lane >> 4;
    uint32_t aAddr[4];
    #pragma unroll
    for (int mt = 0; mt < 4; mt++)
        aAddr[mt] = smem_u32(&As0[(wm*64 + mt*16 + lane15)*SH2]) + lq*16;
    uint32_t bAddr[2];
    {
        int quad = lane >> 3;
        int l7   = lane & 7;
        #pragma unroll
        for (int p = 0; p < 2; p++) {
            int row = wn*32 + (2*p + (quad >> 1))*8 + l7;
            bAddr[p] = smem_u32(&Bs0[row*SH2]) + (quad & 1)*16;
        }
    }

    float acc[4][4][4];
    #pragma unroll
    for (int mt = 0; mt < 4; mt++)
        #pragma unroll
        for (int nt = 0; nt < 4; nt++)
            #pragma unroll
            for (int e = 0; e < 4; e++) acc[mt][nt][e] = 0.f;

    const int KT = K / 32;

    CP_ASYNC16(sA[0], gA); CP_ASYNC16(sA[0] + SROW64, gA + GROW64);
    CP_ASYNC16(sB[0], gB); CP_ASYNC16(sB[0] + SROW64, gB + GROW64);
    CP_COMMIT();

    for (int kt = 0; kt < KT; kt++) {
        int cur = kt & 1;
        if (kt + 1 < KT) {
            int nxt = cur ^ 1;
            size_t go = (size_t)(kt + 1) * 32;
            CP_ASYNC16(sA[nxt], gA + go); CP_ASYNC16(sA[nxt] + SROW64, gA + go + GROW64);
            CP_ASYNC16(sB[nxt], gB + go); CP_ASYNC16(sB[nxt] + SROW64, gB + go + GROW64);
            CP_COMMIT();
            CP_WAIT1();
        } else {
            CP_WAIT0();
        }
        __syncthreads();

        uint32_t stoff = (uint32_t)cur * HSTG_B;
        #pragma unroll
        for (int ks = 0; ks < 2; ks++) {
            uint32_t ko = ks * 32;
            uint32_t af[4][4];
            #pragma unroll
            for (int mt = 0; mt < 4; mt++)
                LDSM_X4(af[mt][0], af[mt][1], af[mt][2], af[mt][3],
                        aAddr[mt] + stoff + ko);
            uint32_t bf[4][2];
            #pragma unroll
            for (int p = 0; p < 2; p++)
                LDSM_X4(bf[2*p][0], bf[2*p][1], bf[2*p+1][0], bf[2*p+1][1],
                        bAddr[p] + stoff + ko);
            #pragma unroll
            for (int mt = 0; mt < 4; mt++)
                #pragma unroll
                for (int nt = 0; nt < 4; nt++)
                    mma_f16(acc[mt][nt], af[mt][0], af[mt][1], af[mt][2], af[mt][3],
                            bf[nt][0], bf[nt][1]);
        }
        __syncthreads();
    }

    #pragma unroll
    for (int mt = 0; mt < 4; mt++) {
        int row = bm + wm*64 + mt*16 + gid;
        #pragma unroll
        for (int nt = 0; nt < 4; nt++) {
            int col = bn + wn*32 + nt*8 + 2*tig;
            float2 bb = {0.f, 0.f};
            if (HAS_BIAS) bb = *(const float2*)&bias[col];
            #pragma unroll
            for (int half_ = 0; half_ < 2; half_++) {
                int rr = row + half_*8;
                float vx = acc[mt][nt][half_*2+0];
                float vy = acc[mt][nt][half_*2+1];
                if (HAS_BIAS) { vx += bb.x; vy += bb.y; }
                if (HAS_GELU) { vx = gelu_f(vx); vy = gelu_f(vy); }
                if (HAS_RES) {
                    float2 rv = *(const float2*)&res[(size_t)rr * N + col];
                    vx += rv.x; vy += rv.y;
                }
                if (OUT_HALF) {
                    __half2* cp = (__half2*)((__half*)Cout + (size_t)rr * N + col);
                    *cp = __floats2half2_rn(vx, vy);
                } else {
                    float2 o2 = {vx, vy};
                    *(float2*)((float*)Cout + (size_t)rr * N + col) = o2;
                }
            }
        }
    }
}

// ======================= fp16 flash attention — ldmatrix fragments =======================
// 8 warps, q-tile 128 (16 q/warp), k-tile 64, D=64. half2 layout, row stride 36 half2.
#define ASQ2  0
#define ASK2  4608
#define ASV2  9216
#define ASVT2 13824
#define ASP2  16128
#define AH2TOT 20736
#define ATTN_BYTES (AH2TOT*4 + 2*64*4)   // 83456
#define KSTG_B (2304u*4u)                // K/V stage stride in bytes (9216)

__global__ void __launch_bounds__(256)
attn_mma(const __half* __restrict__ qkv, const int* __restrict__ gm,
         __half* __restrict__ outp)
{
    extern __shared__ __half2 S[];
    int* smk = (int*)(S + AH2TOT);

    const float SCALE = 0.125f;
    int tid = threadIdx.x, lane = tid & 31, warp = tid >> 5;
    int gid = lane >> 2, tig = lane & 3;
    int bh = blockIdx.y, b = bh >> 4, h = bh & 15;
    int q0 = blockIdx.x * 128;
    int qr = warp*16 + gid;

    // ---- stage Q tile ----
    {
        int r = tid >> 1;
        int sg = (tid & 1) * 4;
        const __half* qp = qkv + (size_t)(b*SEQ + q0 + r) * (3*DIM) + h*HDIM;
        #pragma unroll
        for (int j = 0; j < 4; j++) {
            uint4 w = ((const uint4*)qp)[sg + j];
            *(uint4*)&S[ASQ2 + r*36 + (sg + j)*4] = w;
        }
    }

    auto issue_tile = [&](int kt, int st) {
        int tokbase = b*SEQ + kt*64;
        #pragma unroll
        for (int i = 0; i < 2; i++) {
            int c   = tid + i*256;
            int row = c >> 3;
            int seg = c & 7;
            const __half* kg = qkv + (size_t)(tokbase + row) * (3*DIM) + DIM + h*HDIM + seg*8;
            CP_ASYNC16(smem_u32(&S[ASK2 + st*2304 + row*36 + seg*4]), kg);
            CP_ASYNC16(smem_u32(&S[ASV2 + st*2304 + row*36 + seg*4]), kg + DIM);
        }
        if (tid < 16) {
            CP_ASYNC16(smem_u32(&smk[st*64 + tid*4]), gm + tokbase + tid*4);
        }
    };

    issue_tile(0, 0);
    CP_COMMIT();

    int mq0 = gm[b*SEQ + q0 + qr];
    int mq1 = gm[b*SEQ + q0 + qr + 8];

    float m0 = -FLT_MAX, m1 = -FLT_MAX, l0 = 0.f, l1 = 0.f;
    float acc[8][4];
    #pragma unroll
    for (int nt = 0; nt < 8; nt++)
        acc[nt][0] = acc[nt][1] = acc[nt][2] = acc[nt][3] = 0.f;

    uint32_t* p_u = (uint32_t*)(S + ASP2);

    // ---- ldmatrix fragment addresses (per lane) ----
    int lane15 = lane & 15;
    int lq     = lane >> 4;
    uint32_t aQ = smem_u32(&S[ASQ2 + (warp*16 + lane15)*36]) + lq*16;
    uint32_t aP = smem_u32(&S[ASP2 + (warp*16 + lane15)*36]) + lq*16;
    uint32_t bK[4], bVT[4];
    {
        int quad = lane >> 3;
        int l7   = lane & 7;
        #pragma unroll
        for (int p = 0; p < 4; p++) {
            int row = (2*p + (quad >> 1))*8 + l7;
            bK[p]  = smem_u32(&S[ASK2  + row*36]) + (quad & 1)*16;
            bVT[p] = smem_u32(&S[ASVT2 + row*36]) + (quad & 1)*16;
        }
    }

    for (int kt = 0; kt < 16; kt++) {
        int s = kt & 1;
        CP_WAIT0();
        __syncthreads();

        if (kt < 15) { issue_tile(kt+1, s^1); CP_COMMIT(); }

        // ---- transpose V (2x2 half2 blocks) ----
        {
            int dp = tid & 31;
            int kp0 = tid >> 5;
            const __half2* vsrc = S + ASV2 + s*2304;
            #pragma unroll
            for (int j = 0; j < 4; j++) {
                int kp = kp0 + 8*j;
                __half2 v0 = vsrc[(2*kp)*36 + dp];
                __half2 v1 = vsrc[(2*kp+1)*36 + dp];
                S[ASVT2 + (2*dp)*36 + kp]   = __lows2half2(v0, v1);
                S[ASVT2 + (2*dp+1)*36 + kp] = __highs2half2(v0, v1);
            }
        }
        __syncthreads();

        // ---- S = Q @ K^T (LDSM fragments) ----
        float sc[8][4];
        #pragma unroll
        for (int nt = 0; nt < 8; nt++)
            sc[nt][0] = sc[nt][1] = sc[nt][2] = sc[nt][3] = 0.f;
        {
            uint32_t stg = (uint32_t)s * KSTG_B;
            #pragma unroll
            for (int ks = 0; ks < 4; ks++) {
                uint32_t ko = ks * 32;
                uint32_t a0, a1, a2, a3;
                LDSM_X4(a0, a1, a2, a3, aQ + ko);
                #pragma unroll
                for (int p = 0; p < 4; p++) {
                    uint32_t b0, b1, b2, b3;
                    LDSM_X4(b0, b1, b2, b3, bK[p] + stg + ko);
                    mma_f16(sc[2*p],   a0, a1, a2, a3, b0, b1);
                    mma_f16(sc[2*p+1], a0, a1, a2, a3, b2, b3);
                }
            }
        }

        // ---- mask + online softmax ----
        float mx0 = -FLT_MAX, mx1 = -FLT_MAX;
        #pragma unroll
        for (int nt = 0; nt < 8; nt++) {
            int kk = 8*nt + 2*tig;
            int ka_ = smk[s*64 + kk], kb_ = smk[s*64 + kk + 1];
            sc[nt][0] = (mq0 && ka_) ? sc[nt][0]*SCALE : -FLT_MAX;
            sc[nt][1] = (mq0 && kb_) ? sc[nt][1]*SCALE : -FLT_MAX;
            sc[nt][2] = (mq1 && ka_) ? sc[nt][2]*SCALE : -FLT_MAX;
            sc[nt][3] = (mq1 && kb_) ? sc[nt][3]*SCALE : -FLT_MAX;
            mx0 = fmaxf(mx0, fmaxf(sc[nt][0], sc[nt][1]));
            mx1 = fmaxf(mx1, fmaxf(sc[nt][2], sc[nt][3]));
        }
        mx0 = fmaxf(mx0, __shfl_xor_sync(0xffffffffu, mx0, 1));
        mx0 = fmaxf(mx0, __shfl_xor_sync(0xffffffffu, mx0, 2));
        mx1 = fmaxf(mx1, __shfl_xor_sync(0xffffffffu, mx1, 1));
        mx1 = fmaxf(mx1, __shfl_xor_sync(0xffffffffu, mx1, 2));

        float mn0 = fmaxf(m0, mx0), mn1 = fmaxf(m1, mx1);
        float c0 = __expf(m0 - mn0), c1 = __expf(m1 - mn1);
        float ps0 = 0.f, ps1 = 0.f;
        #pragma unroll
        for (int nt = 0; nt < 8; nt++) {
            float p00 = __expf(sc[nt][0] - mn0);
            float p01 = __expf(sc[nt][1] - mn0);
            float p10 = __expf(sc[nt][2] - mn1);
            float p11 = __expf(sc[nt][3] - mn1);
            ps0 += p00 + p01; ps1 += p10 + p11;
            int cp = 4*nt + tig;
            p_u[qr*36 + cp]     = h2_u32(__floats2half2_rn(p00, p01));
            p_u[(qr+8)*36 + cp] = h2_u32(__floats2half2_rn(p10, p11));
        }
        ps0 += __shfl_xor_sync(0xffffffffu, ps0, 1);
        ps0 += __shfl_xor_sync(0xffffffffu, ps0, 2);
        ps1 += __shfl_xor_sync(0xffffffffu, ps1, 1);
        ps1 += __shfl_xor_sync(0xffffffffu, ps1, 2);
        l0 = l0*c0 + ps0; l1 = l1*c1 + ps1;
        m0 = mn0; m1 = mn1;
        #pragma unroll
        for (int nt = 0; nt < 8; nt++) {
            acc[nt][0] *= c0; acc[nt][1] *= c0;
            acc[nt][2] *= c1; acc[nt][3] *= c1;
        }
        __syncwarp();

        // ---- O += P @ V^T (LDSM fragments) ----
        #pragma unroll
        for (int ks = 0; ks < 4; ks++) {
            uint32_t ko = ks * 32;
            uint32_t a0, a1, a2, a3;
            LDSM_X4(a0, a1, a2, a3, aP + ko);
            #pragma unroll
            for (int p = 0; p < 4; p++) {
                uint32_t b0, b1, b2, b3;
                LDSM_X4(b0, b1, b2, b3, bVT[p] + ko);
                mma_f16(acc[2*p],   a0, a1, a2, a3, b0, b1);
                mma_f16(acc[2*p+1], a0, a1, a2, a3, b2, b3);
            }
        }
    }

    float inv0 = 1.0f / l0, inv1 = 1.0f / l1;
    __half2* op0 = (__half2*)(outp + (size_t)(b*SEQ + q0 + qr) * DIM + h*HDIM);
    __half2* op1 = (__half2*)(outp + (size_t)(b*SEQ + q0 + qr + 8) * DIM + h*HDIM);
    #pragma unroll
    for (int nt = 0; nt < 8; nt++) {
        int cp = 4*nt + tig;
        op0[cp] = __floats2half2_rn(acc[nt][0]*inv0, acc[nt][1]*inv0);
        op1[cp] = __floats2half2_rn(acc[nt][2]*inv1, acc[nt][3]*inv1);
    }
}

// ======================= host side =======================
extern "C" void kernel_launch(void* const* d_in, const int* in_sizes, int n_in,
                              void* d_out, int out_size)
{
    const float* src   = (const float*)d_in[0];
    const unsigned char* maskraw = (const unsigned char*)d_in[1];
    const float* Wqkv  = (const float*)d_in[2];
    const float* Wproj = (const float*)d_in[3];
    const float* bproj = (const float*)d_in[4];
    const float* W1    = (const float*)d_in[5];
    const float* b1    = (const float*)d_in[6];
    const float* W2    = (const float*)d_in[7];
    const float* b2    = (const float*)d_in[8];
    const float* g0    = (const float*)d_in[9];
    const float* beta0 = (const float*)d_in[10];
    const float* g1    = (const float*)d_in[11];
    const float* beta1 = (const float*)d_in[12];
    float* out = (float*)d_out;

    __half *ln, *qkv, *att, *ffn, *wq, *wp, *w1c, *w2c;
    float *ln32, *x; int* msk;
    cudaGetSymbolAddress((void**)&ln,   g_ln);
    cudaGetSymbolAddress((void**)&ln32, g_ln32);
    cudaGetSymbolAddress((void**)&qkv,  g_qkv);
    cudaGetSymbolAddress((void**)&att,  g_att);
    cudaGetSymbolAddress((void**)&x,    g_x);
    cudaGetSymbolAddress((void**)&ffn,  g_ffn);
    cudaGetSymbolAddress((void**)&msk,  g_msk);
    cudaGetSymbolAddress((void**)&wq,   g_wq);
    cudaGetSymbolAddress((void**)&wp,   g_wp);
    cudaGetSymbolAddress((void**)&w1c,  g_w1);
    cudaGetSymbolAddress((void**)&w2c,  g_w2);

    cudaFuncSetAttribute(attn_mma, cudaFuncAttributeMaxDynamicSharedMemorySize, ATTN_BYTES);

    // 0. weights -> fp16 (one launch)
    {
        int n0 = 3*DIM*DIM/4, n1 = DIM*DIM/4, n2 = FDIM*DIM/4, n3 = DIM*FDIM/4;
        int ntot = n0 + n1 + n2 + n3;
        cvt_all_kernel<<<(ntot + 255)/256, 256>>>(
            (const float4*)Wqkv,  (__half2*)wq,  n0,
            (const float4*)Wproj, (__half2*)wp,  n1,
            (const float4*)W1,    (__half2*)w1c, n2,
            (const float4*)W2,    (__half2*)w2c, n3);
    }
    // 1. normalize mask
    mask_kernel<<<1, 256>>>(maskraw, msk);
    // 2. LN0 (half out)
    ln_kernel<false><<<TOK, 256>>>(src, g0, beta0, ln, nullptr);
    // 3. QKV projection -> half
    gemm_mma<3*DIM, DIM, false, false, false, true>
        <<<dim3(3*DIM/128, TOK/128), 256, GSMEM_BYTES>>>(ln, wq, nullptr, nullptr, qkv);
    // 4. attention (fp16 tensor-core flash, half out)
    attn_mma<<<dim3(SEQ/128, BATCH*NHEAD), 256, ATTN_BYTES>>>(qkv, msk, att);
    // 5. output projection + bias + residual(src) -> x (fp32)
    gemm_mma<DIM, DIM, true, false, true, false>
        <<<dim3(DIM/128, TOK/128), 256, GSMEM_BYTES>>>(att, wp, bproj, src, x);
    // 6. LN1 (half out + fp32 copy for FFN residual)
    ln_kernel<true><<<TOK, 256>>>(x, g1, beta1, ln, ln32);
    // 7. FFN1 + bias + exact GELU -> half
    gemm_mma<FDIM, DIM, true, true, false, true>
        <<<dim3(FDIM/128, TOK/128), 256, GSMEM_BYTES>>>(ln, w1c, b1, nullptr, ffn);
    // 8. FFN2 + bias + residual(LN1 fp32) -> out (fp32)
    gemm_mma<DIM, FDIM, true, false, true, false>
        <<<dim3(DIM/128, TOK/128), 256, GSMEM_BYTES>>>(ffn, w2c, b2, ln32, out);
}

// round 16
// speedup vs baseline: 1.1914x; 1.0279x over previous
#include <cuda_runtime.h>
#include <cuda_fp16.h>
#include <cfloat>
#include <math.h>
#include <stdint.h>

// Problem constants
#define BATCH 8
#define SEQ   1024
#define DIM   1024
#define NHEAD 16
#define HDIM  64
#define FDIM  4096
#define TOK   (BATCH*SEQ)   // 8192

// ---------------- scratch (static device globals; no allocation) ----------------
__device__ __half g_ln  [(size_t)TOK * DIM];    // LN out (half, feeds GEMM)
__device__ float  g_ln32[(size_t)TOK * DIM];    // LN1 fp32 copy (FFN2 residual)
__device__ __half g_qkv [(size_t)TOK * 3*DIM];  // qkv (half — feeds fp16 attention)
__device__ __half g_att [(size_t)TOK * DIM];    // attention out (half)
__device__ float  g_x   [(size_t)TOK * DIM];    // src + proj(att) (fp32)
__device__ __half g_ffn [(size_t)TOK * FDIM];   // GELU(FFN1) (half)
__device__ int    g_msk [TOK];
// half weight copies
__device__ __half g_wq[(size_t)3*DIM*DIM];
__device__ __half g_wp[(size_t)DIM*DIM];
__device__ __half g_w1[(size_t)FDIM*DIM];
__device__ __half g_w2[(size_t)DIM*FDIM];

// ======================= small helpers =======================
__device__ __forceinline__ uint32_t smem_u32(const void* p) {
    uint32_t a;
    asm("{ .reg .u64 t; cvta.to.shared.u64 t, %1; cvt.u32.u64 %0, t; }" : "=r"(a) : "l"(p));
    return a;
}

__device__ __forceinline__ uint32_t h2_u32(__half2 h) {
    uint32_t u;
    memcpy(&u, &h, 4);
    return u;
}

__device__ __forceinline__ void mma_f16(float c[4],
                                        uint32_t a0, uint32_t a1, uint32_t a2, uint32_t a3,
                                        uint32_t b0, uint32_t b1) {
    asm volatile(
        "mma.sync.aligned.m16n8k16.row.col.f32.f16.f16.f32 "
        "{%0,%1,%2,%3}, {%4,%5,%6,%7}, {%8,%9}, {%0,%1,%2,%3};"
        : "+f"(c[0]), "+f"(c[1]), "+f"(c[2]), "+f"(c[3])
        : "r"(a0), "r"(a1), "r"(a2), "r"(a3), "r"(b0), "r"(b1));
}

#define LDSM_X4(r0, r1, r2, r3, addr) \
    asm volatile("ldmatrix.sync.aligned.m8n8.x4.shared.b16 {%0,%1,%2,%3}, [%4];" \
        : "=r"(r0), "=r"(r1), "=r"(r2), "=r"(r3) : "r"(addr))

#define LDSM_X4_T(r0, r1, r2, r3, addr) \
    asm volatile("ldmatrix.sync.aligned.m8n8.x4.trans.shared.b16 {%0,%1,%2,%3}, [%4];" \
        : "=r"(r0), "=r"(r1), "=r"(r2), "=r"(r3) : "r"(addr))

#define CP_ASYNC16(saddr, gptr) \
    asm volatile("cp.async.cg.shared.global [%0], [%1], 16;" :: "r"(saddr), "l"(gptr))
#define CP_COMMIT() asm volatile("cp.async.commit_group;")
#define CP_WAIT1()  asm volatile("cp.async.wait_group 1;")
#define CP_WAIT0()  asm volatile("cp.async.wait_group 0;")

__device__ __forceinline__ float gelu_f(float x)
{
    return 0.5f * x * (1.0f + erff(x * 0.70710678118654752f));
}

// ---------------- fp32 -> fp16 conversion of ALL weights in one launch ----------------
__global__ void cvt_all_kernel(const float4* __restrict__ i0, __half2* __restrict__ o0, int n0,
                               const float4* __restrict__ i1, __half2* __restrict__ o1, int n1,
                               const float4* __restrict__ i2, __half2* __restrict__ o2, int n2,
                               const float4* __restrict__ i3, __half2* __restrict__ o3, int n3)
{
    int idx = blockIdx.x * blockDim.x + threadIdx.x;
    const float4* in; __half2* out;
    if (idx < n0)              { in = i0; out = o0; }
    else if ((idx -= n0) < n1) { in = i1; out = o1; }
    else if ((idx -= n1) < n2) { in = i2; out = o2; }
    else if ((idx -= n2) < n3) { in = i3; out = o3; }
    else return;
    float4 v = in[idx];
    out[2*idx]   = __floats2half2_rn(v.x, v.y);
    out[2*idx+1] = __floats2half2_rn(v.z, v.w);
}

// ---------------- mask dtype detection + normalization ----------------
__global__ void mask_kernel(const unsigned char* __restrict__ raw, int* __restrict__ gm)
{
    __shared__ int cnt[4];
    int t = threadIdx.x;
    if (t < 4) cnt[t] = 0;
    __syncthreads();
    int l1=0, l2=0, l3=0, lb=0;
    for (int i = t; i < TOK; i += blockDim.x) {
        unsigned char bch = raw[i];
        if (bch) {
            int m = i & 3;
            if (m == 1) l1++;
            else if (m == 2) l2++;
            else if (m == 3) l3++;
            if (bch > 1) lb++;
        }
    }
    atomicAdd(&cnt[0], l1); atomicAdd(&cnt[1], l2);
    atomicAdd(&cnt[2], l3); atomicAdd(&cnt[3], lb);
    __syncthreads();
    int c1 = cnt[0], c2 = cnt[1], c3 = cnt[2], cb = cnt[3];
    int type;
    if (c1 < 64 && c2 < 64 && c3 < 64) type = 0;
    else if (c1 < 64)                  type = 1;
    else if (cb < 64)                  type = 2;
    else                               type = 3;
    for (int i = t; i < TOK; i += blockDim.x) {
        int v;
        if      (type == 0) v = (((const int*)raw)[i] != 0);
        else if (type == 1) v = (((const float*)raw)[i] != 0.0f);
        else if (type == 2) v = (raw[i] != 0);
        else                v = (((const unsigned short*)raw)[i] != 0);
        gm[i] = v;
    }
}

// ---------------- LayerNorm: half out (+ optional fp32 copy) ----------------
template<bool WF>
__global__ void ln_kernel(const float* __restrict__ in,
                          const float* __restrict__ gamma,
                          const float* __restrict__ beta,
                          __half* __restrict__ outh,
                          float* __restrict__ outf)
{
    int row = blockIdx.x;
    int t = threadIdx.x;
    const float* xr = in + (size_t)row * DIM;
    float4 v = ((const float4*)xr)[t];
    float s = v.x + v.y + v.z + v.w;
    float q = v.x*v.x + v.y*v.y + v.z*v.z + v.w*v.w;
    #pragma unroll
    for (int o = 16; o; o >>= 1) {
        s += __shfl_xor_sync(0xffffffffu, s, o);
        q += __shfl_xor_sync(0xffffffffu, q, o);
    }
    __shared__ float ss[8], qq[8];
    if ((t & 31) == 0) { ss[t >> 5] = s; qq[t >> 5] = q; }
    __syncthreads();
    s = 0.f; q = 0.f;
    #pragma unroll
    for (int i = 0; i < 8; i++) { s += ss[i]; q += qq[i]; }
    float mean = s * (1.0f / DIM);
    float var  = q * (1.0f / DIM) - mean * mean;
    float rstd = rsqrtf(var + 1e-5f);
    float4 gv = ((const float4*)gamma)[t];
    float4 bv = ((const float4*)beta)[t];
    float ox = (v.x - mean) * rstd * gv.x + bv.x;
    float oy = (v.y - mean) * rstd * gv.y + bv.y;
    float oz = (v.z - mean) * rstd * gv.z + bv.z;
    float ow = (v.w - mean) * rstd * gv.w + bv.w;
    __half2* oh = (__half2*)(outh + (size_t)row * DIM);
    oh[2*t]   = __floats2half2_rn(ox, oy);
    oh[2*t+1] = __floats2half2_rn(oz, ow);
    if (WF) {
        float4 o = {ox, oy, oz, ow};
        ((float4*)(outf + (size_t)row * DIM))[t] = o;
    }
}

// ======================= FP16 mma.sync GEMM (byte-exact R11/R15 winner) =======================
#define SH2 20
#define HSTG (128*SH2)                    // half2 per matrix per stage (2560)
#define HSTG_B (HSTG*4)                   // stage stride in bytes (10240)
#define GSMEM_BYTES (4*HSTG*4)            // 40960

template<int N, int K, bool HAS_BIAS, bool HAS_GELU, bool HAS_RES, bool OUT_HALF>
__global__ void __launch_bounds__(256, 2)
gemm_mma(const __half* __restrict__ A, const __half* __restrict__ Bm,
         const float* __restrict__ bias, const float* __restrict__ res,
         void* __restrict__ Cout)
{
    extern __shared__ __half2 sh[];
    __half2* As0 = sh;
    __half2* Bs0 = sh + 2*HSTG;

    int tid  = threadIdx.x;
    int lane = tid & 31, warp = tid >> 5;
    int wm = warp >> 2, wn = warp & 3;
    int gid = lane >> 2, tig = lane & 3;
    int bm = blockIdx.y * 128, bn = blockIdx.x * 128;

    int lrow = tid >> 2;          // 0..63
    int lseg = tid & 3;           // 0..3
    const __half* gA = A  + (size_t)(bm + lrow) * K + lseg * 8;
    const __half* gB = Bm + (size_t)(bn + lrow) * K + lseg * 8;
    uint32_t sA[2], sB[2];
    #pragma unroll
    for (int st = 0; st < 2; st++) {
        sA[st] = smem_u32(&As0[st*HSTG + lrow*SH2 + lseg*4]);
        sB[st] = smem_u32(&Bs0[st*HSTG + lrow*SH2 + lseg*4]);
    }
    const uint32_t SROW64 = 64u * SH2 * 4u;
    const size_t  GROW64 = (size_t)64 * K;

    int lane15 = lane & 15;
    int lq     = lane >> 4;
    uint32_t aAddr[4];
    #pragma unroll
    for (int mt = 0; mt < 4; mt++)
        aAddr[mt] = smem_u32(&As0[(wm*64 + mt*16 + lane15)*SH2]) + lq*16;
    uint32_t bAddr[2];
    {
        int quad = lane >> 3;
        int l7   = lane & 7;
        #pragma unroll
        for (int p = 0; p < 2; p++) {
            int row = wn*32 + (2*p + (quad >> 1))*8 + l7;
            bAddr[p] = smem_u32(&Bs0[row*SH2]) + (quad & 1)*16;
        }
    }

    float acc[4][4][4];
    #pragma unroll
    for (int mt = 0; mt < 4; mt++)
        #pragma unroll
        for (int nt = 0; nt < 4; nt++)
            #pragma unroll
            for (int e = 0; e < 4; e++) acc[mt][nt][e] = 0.f;

    const int KT = K / 32;

    CP_ASYNC16(sA[0], gA); CP_ASYNC16(sA[0] + SROW64, gA + GROW64);
    CP_ASYNC16(sB[0], gB); CP_ASYNC16(sB[0] + SROW64, gB + GROW64);
    CP_COMMIT();

    for (int kt = 0; kt < KT; kt++) {
        int cur = kt & 1;
        if (kt + 1 < KT) {
            int nxt = cur ^ 1;
            size_t go = (size_t)(kt + 1) * 32;
            CP_ASYNC16(sA[nxt], gA + go); CP_ASYNC16(sA[nxt] + SROW64, gA + go + GROW64);
            CP_ASYNC16(sB[nxt], gB + go); CP_ASYNC16(sB[nxt] + SROW64, gB + go + GROW64);
            CP_COMMIT();
            CP_WAIT1();
        } else {
            CP_WAIT0();
        }
        __syncthreads();

        uint32_t stoff = (uint32_t)cur * HSTG_B;
        #pragma unroll
        for (int ks = 0; ks < 2; ks++) {
            uint32_t ko = ks * 32;
            uint32_t af[4][4];
            #pragma unroll
            for (int mt = 0; mt < 4; mt++)
                LDSM_X4(af[mt][0], af[mt][1], af[mt][2], af[mt][3],
                        aAddr[mt] + stoff + ko);
            uint32_t bf[4][2];
            #pragma unroll
            for (int p = 0; p < 2; p++)
                LDSM_X4(bf[2*p][0], bf[2*p][1], bf[2*p+1][0], bf[2*p+1][1],
                        bAddr[p] + stoff + ko);
            #pragma unroll
            for (int mt = 0; mt < 4; mt++)
                #pragma unroll
                for (int nt = 0; nt < 4; nt++)
                    mma_f16(acc[mt][nt], af[mt][0], af[mt][1], af[mt][2], af[mt][3],
                            bf[nt][0], bf[nt][1]);
        }
        __syncthreads();
    }

    #pragma unroll
    for (int mt = 0; mt < 4; mt++) {
        int row = bm + wm*64 + mt*16 + gid;
        #pragma unroll
        for (int nt = 0; nt < 4; nt++) {
            int col = bn + wn*32 + nt*8 + 2*tig;
            float2 bb = {0.f, 0.f};
            if (HAS_BIAS) bb = *(const float2*)&bias[col];
            #pragma unroll
            for (int half_ = 0; half_ < 2; half_++) {
                int rr = row + half_*8;
                float vx = acc[mt][nt][half_*2+0];
                float vy = acc[mt][nt][half_*2+1];
                if (HAS_BIAS) { vx += bb.x; vy += bb.y; }
                if (HAS_GELU) { vx = gelu_f(vx); vy = gelu_f(vy); }
                if (HAS_RES) {
                    float2 rv = *(const float2*)&res[(size_t)rr * N + col];
                    vx += rv.x; vy += rv.y;
                }
                if (OUT_HALF) {
                    __half2* cp = (__half2*)((__half*)Cout + (size_t)rr * N + col);
                    *cp = __floats2half2_rn(vx, vy);
                } else {
                    float2 o2 = {vx, vy};
                    *(float2*)((float*)Cout + (size_t)rr * N + col) = o2;
                }
            }
        }
    }
}

// ======================= fp16 flash attention — trans-LDSM V (no transpose phase) =======================
// 8 warps, q-tile 128 (16 q/warp), k-tile 64, D=64. half2 layout, row stride 36 half2.
#define ASQ2  0
#define ASK2  4608
#define ASV2  9216
#define ASP2  16128
#define AH2TOT 20736
#define ATTN_BYTES (AH2TOT*4 + 2*64*4)   // 83456
#define KSTG_B (2304u*4u)                // K/V stage stride in bytes (9216)
#define VROW16 (16u*36u*4u)              // 16 V rows in bytes (2304)

__global__ void __launch_bounds__(256)
attn_mma(const __half* __restrict__ qkv, const int* __restrict__ gm,
         __half* __restrict__ outp)
{
    extern __shared__ __half2 S[];
    int* smk = (int*)(S + AH2TOT);

    const float SCALE = 0.125f;
    int tid = threadIdx.x, lane = tid & 31, warp = tid >> 5;
    int gid = lane >> 2, tig = lane & 3;
    int bh = blockIdx.y, b = bh >> 4, h = bh & 15;
    int q0 = blockIdx.x * 128;
    int qr = warp*16 + gid;

    // ---- stage Q tile ----
    {
        int r = tid >> 1;
        int sg = (tid & 1) * 4;
        const __half* qp = qkv + (size_t)(b*SEQ + q0 + r) * (3*DIM) + h*HDIM;
        #pragma unroll
        for (int j = 0; j < 4; j++) {
            uint4 w = ((const uint4*)qp)[sg + j];
            *(uint4*)&S[ASQ2 + r*36 + (sg + j)*4] = w;
        }
    }

    auto issue_tile = [&](int kt, int st) {
        int tokbase = b*SEQ + kt*64;
        #pragma unroll
        for (int i = 0; i < 2; i++) {
            int c   = tid + i*256;
            int row = c >> 3;
            int seg = c & 7;
            const __half* kg = qkv + (size_t)(tokbase + row) * (3*DIM) + DIM + h*HDIM + seg*8;
            CP_ASYNC16(smem_u32(&S[ASK2 + st*2304 + row*36 + seg*4]), kg);
            CP_ASYNC16(smem_u32(&S[ASV2 + st*2304 + row*36 + seg*4]), kg + DIM);
        }
        if (tid < 16) {
            CP_ASYNC16(smem_u32(&smk[st*64 + tid*4]), gm + tokbase + tid*4);
        }
    };

    issue_tile(0, 0);
    CP_COMMIT();

    int mq0 = gm[b*SEQ + q0 + qr];
    int mq1 = gm[b*SEQ + q0 + qr + 8];

    float m0 = -FLT_MAX, m1 = -FLT_MAX, l0 = 0.f, l1 = 0.f;
    float acc[8][4];
    #pragma unroll
    for (int nt = 0; nt < 8; nt++)
        acc[nt][0] = acc[nt][1] = acc[nt][2] = acc[nt][3] = 0.f;

    uint32_t* p_u = (uint32_t*)(S + ASP2);

    // ---- ldmatrix fragment addresses (per lane) ----
    int lane15 = lane & 15;
    int lq     = lane >> 4;
    uint32_t aQ = smem_u32(&S[ASQ2 + (warp*16 + lane15)*36]) + lq*16;
    uint32_t aP = smem_u32(&S[ASP2 + (warp*16 + lane15)*36]) + lq*16;
    int quad = lane >> 3;
    int l7   = lane & 7;
    uint32_t bK[4];
    #pragma unroll
    for (int p = 0; p < 4; p++) {
        int row = (2*p + (quad >> 1))*8 + l7;
        bK[p] = smem_u32(&S[ASK2 + row*36]) + (quad & 1)*16;
    }
    // V trans fragments: matrix mj = V[key 8-block][d 16B block]^T
    // m0=(keys 0-7, d=32p B), m1=(keys 8-15, same d), m2=(keys 0-7, d+16B), m3=(keys 8-15, d+16B)
    uint32_t bV[4];
    #pragma unroll
    for (int p = 0; p < 4; p++) {
        int vrow = (quad & 1)*8 + l7;           // key within 16-block
        bV[p] = smem_u32(&S[ASV2 + vrow*36]) + 32*p + (quad >> 1)*16;
    }

    for (int kt = 0; kt < 16; kt++) {
        int s = kt & 1;
        CP_WAIT0();
        __syncthreads();    // K/V tile s ready; all warps done reading tile s (prev use)

        if (kt < 15) { issue_tile(kt+1, s^1); CP_COMMIT(); }

        // ---- S = Q @ K^T (LDSM fragments) ----
        float sc[8][4];
        #pragma unroll
        for (int nt = 0; nt < 8; nt++)
            sc[nt][0] = sc[nt][1] = sc[nt][2] = sc[nt][3] = 0.f;
        {
            uint32_t stg = (uint32_t)s * KSTG_B;
            #pragma unroll
            for (int ks = 0; ks < 4; ks++) {
                uint32_t ko = ks * 32;
                uint32_t a0, a1, a2, a3;
                LDSM_X4(a0, a1, a2, a3, aQ + ko);
                #pragma unroll
                for (int p = 0; p < 4; p++) {
                    uint32_t b0, b1, b2, b3;
                    LDSM_X4(b0, b1, b2, b3, bK[p] + stg + ko);
                    mma_f16(sc[2*p],   a0, a1, a2, a3, b0, b1);
                    mma_f16(sc[2*p+1], a0, a1, a2, a3, b2, b3);
                }
            }
        }

        // ---- mask + online softmax ----
        float mx0 = -FLT_MAX, mx1 = -FLT_MAX;
        #pragma unroll
        for (int nt = 0; nt < 8; nt++) {
            int kk = 8*nt + 2*tig;
            int ka_ = smk[s*64 + kk], kb_ = smk[s*64 + kk + 1];
            sc[nt][0] = (mq0 && ka_) ? sc[nt][0]*SCALE : -FLT_MAX;
            sc[nt][1] = (mq0 && kb_) ? sc[nt][1]*SCALE : -FLT_MAX;
            sc[nt][2] = (mq1 && ka_) ? sc[nt][2]*SCALE : -FLT_MAX;
            sc[nt][3] = (mq1 && kb_) ? sc[nt][3]*SCALE : -FLT_MAX;
            mx0 = fmaxf(mx0, fmaxf(sc[nt][0], sc[nt][1]));
            mx1 = fmaxf(mx1, fmaxf(sc[nt][2], sc[nt][3]));
        }
        mx0 = fmaxf(mx0, __shfl_xor_sync(0xffffffffu, mx0, 1));
        mx0 = fmaxf(mx0, __shfl_xor_sync(0xffffffffu, mx0, 2));
        mx1 = fmaxf(mx1, __shfl_xor_sync(0xffffffffu, mx1, 1));
        mx1 = fmaxf(mx1, __shfl_xor_sync(0xffffffffu, mx1, 2));

        float mn0 = fmaxf(m0, mx0), mn1 = fmaxf(m1, mx1);
        float c0 = __expf(m0 - mn0), c1 = __expf(m1 - mn1);
        float ps0 = 0.f, ps1 = 0.f;
        #pragma unroll
        for (int nt = 0; nt < 8; nt++) {
            float p00 = __expf(sc[nt][0] - mn0);
            float p01 = __expf(sc[nt][1] - mn0);
            float p10 = __expf(sc[nt][2] - mn1);
            float p11 = __expf(sc[nt][3] - mn1);
            ps0 += p00 + p01; ps1 += p10 + p11;
            int cp = 4*nt + tig;
            p_u[qr*36 + cp]     = h2_u32(__floats2half2_rn(p00, p01));
            p_u[(qr+8)*36 + cp] = h2_u32(__floats2half2_rn(p10, p11));
        }
        ps0 += __shfl_xor_sync(0xffffffffu, ps0, 1);
        ps0 += __shfl_xor_sync(0xffffffffu, ps0, 2);
        ps1 += __shfl_xor_sync(0xffffffffu, ps1, 1);
        ps1 += __shfl_xor_sync(0xffffffffu, ps1, 2);
        l0 = l0*c0 + ps0; l1 = l1*c1 + ps1;
        m0 = mn0; m1 = mn1;
        #pragma unroll
        for (int nt = 0; nt < 8; nt++) {
            acc[nt][0] *= c0; acc[nt][1] *= c0;
            acc[nt][2] *= c1; acc[nt][3] *= c1;
        }
        __syncwarp();   // P is warp-private: STS -> LDSM visibility

        // ---- O += P @ V (trans-LDSM directly on row-major sV) ----
        {
            uint32_t stg = (uint32_t)s * KSTG_B;
            #pragma unroll
            for (int ks = 0; ks < 4; ks++) {
                uint32_t ko = ks * 32;          // P fragment k-offset (bytes)
                uint32_t vo = ks * VROW16;      // V 16-key-row block offset
                uint32_t a0, a1, a2, a3;
                LDSM_X4(a0, a1, a2, a3, aP + ko);
                #pragma unroll
                for (int p = 0; p < 4; p++) {
                    uint32_t b0, b1, b2, b3;
                    LDSM_X4_T(b0, b1, b2, b3, bV[p] + stg + vo);
                    mma_f16(acc[2*p],   a0, a1, a2, a3, b0, b1);
                    mma_f16(acc[2*p+1], a0, a1, a2, a3, b2, b3);
                }
            }
        }
    }

    float inv0 = 1.0f / l0, inv1 = 1.0f / l1;
    __half2* op0 = (__half2*)(outp + (size_t)(b*SEQ + q0 + qr) * DIM + h*HDIM);
    __half2* op1 = (__half2*)(outp + (size_t)(b*SEQ + q0 + qr + 8) * DIM + h*HDIM);
    #pragma unroll
    for (int nt = 0; nt < 8; nt++) {
        int cp = 4*nt + tig;
        op0[cp] = __floats2half2_rn(acc[nt][0]*inv0, acc[nt][1]*inv0);
        op1[cp] = __floats2half2_rn(acc[nt][2]*inv1, acc[nt][3]*inv1);
    }
}

// ======================= host side =======================
extern "C" void kernel_launch(void* const* d_in, const int* in_sizes, int n_in,
                              void* d_out, int out_size)
{
    const float* src   = (const float*)d_in[0];
    const unsigned char* maskraw = (const unsigned char*)d_in[1];
    const float* Wqkv  = (const float*)d_in[2];
    const float* Wproj = (const float*)d_in[3];
    const float* bproj = (const float*)d_in[4];
    const float* W1    = (const float*)d_in[5];
    const float* b1    = (const float*)d_in[6];
    const float* W2    = (const float*)d_in[7];
    const float* b2    = (const float*)d_in[8];
    const float* g0    = (const float*)d_in[9];
    const float* beta0 = (const float*)d_in[10];
    const float* g1    = (const float*)d_in[11];
    const float* beta1 = (const float*)d_in[12];
    float* out = (float*)d_out;

    __half *ln, *qkv, *att, *ffn, *wq, *wp, *w1c, *w2c;
    float *ln32, *x; int* msk;
    cudaGetSymbolAddress((void**)&ln,   g_ln);
    cudaGetSymbolAddress((void**)&ln32, g_ln32);
    cudaGetSymbolAddress((void**)&qkv,  g_qkv);
    cudaGetSymbolAddress((void**)&att,  g_att);
    cudaGetSymbolAddress((void**)&x,    g_x);
    cudaGetSymbolAddress((void**)&ffn,  g_ffn);
    cudaGetSymbolAddress((void**)&msk,  g_msk);
    cudaGetSymbolAddress((void**)&wq,   g_wq);
    cudaGetSymbolAddress((void**)&wp,   g_wp);
    cudaGetSymbolAddress((void**)&w1c,  g_w1);
    cudaGetSymbolAddress((void**)&w2c,  g_w2);

    cudaFuncSetAttribute(attn_mma, cudaFuncAttributeMaxDynamicSharedMemorySize, ATTN_BYTES);

    // 0. weights -> fp16 (one launch)
    {
        int n0 = 3*DIM*DIM/4, n1 = DIM*DIM/4, n2 = FDIM*DIM/4, n3 = DIM*FDIM/4;
        int ntot = n0 + n1 + n2 + n3;
        cvt_all_kernel<<<(ntot + 255)/256, 256>>>(
            (const float4*)Wqkv,  (__half2*)wq,  n0,
            (const float4*)Wproj, (__half2*)wp,  n1,
            (const float4*)W1,    (__half2*)w1c, n2,
            (const float4*)W2,    (__half2*)w2c, n3);
    }
    // 1. normalize mask
    mask_kernel<<<1, 256>>>(maskraw, msk);
    // 2. LN0 (half out)
    ln_kernel<false><<<TOK, 256>>>(src, g0, beta0, ln, nullptr);
    // 3. QKV projection -> half
    gemm_mma<3*DIM, DIM, false, false, false, true>
        <<<dim3(3*DIM/128, TOK/128), 256, GSMEM_BYTES>>>(ln, wq, nullptr, nullptr, qkv);
    // 4. attention (fp16 tensor-core flash, half out)
    attn_mma<<<dim3(SEQ/128, BATCH*NHEAD), 256, ATTN_BYTES>>>(qkv, msk, att);
    // 5. output projection + bias + residual(src) -> x (fp32)
    gemm_mma<DIM, DIM, true, false, true, false>
        <<<dim3(DIM/128, TOK/128), 256, GSMEM_BYTES>>>(att, wp, bproj, src, x);
    // 6. LN1 (half out + fp32 copy for FFN residual)
    ln_kernel<true><<<TOK, 256>>>(x, g1, beta1, ln, ln32);
    // 7. FFN1 + bias + exact GELU -> half
    gemm_mma<FDIM, DIM, true, true, false, true>
        <<<dim3(FDIM/128, TOK/128), 256, GSMEM_BYTES>>>(ln, w1c, b1, nullptr, ffn);
    // 8. FFN2 + bias + residual(LN1 fp32) -> out (fp32)
    gemm_mma<DIM, FDIM, true, false, true, false>
        <<<dim3(DIM/128, TOK/128), 256, GSMEM_BYTES>>>(ffn, w2c, b2, ln32, out);
}

// round 17
// speedup vs baseline: 1.2749x; 1.0701x over previous
#include <cuda_runtime.h>
#include <cuda_fp16.h>
#include <cfloat>
#include <math.h>
#include <stdint.h>

// Problem constants
#define BATCH 8
#define SEQ   1024
#define DIM   1024
#define NHEAD 16
#define HDIM  64
#define FDIM  4096
#define TOK   (BATCH*SEQ)   // 8192

// ---------------- scratch (static device globals; no allocation) ----------------
__device__ __half g_ln  [(size_t)TOK * DIM];    // LN out (half; also FFN2 residual)
__device__ __half g_qkv [(size_t)TOK * 3*DIM];  // qkv (half)
__device__ __half g_att [(size_t)TOK * DIM];    // attention out (half)
__device__ float  g_x   [(size_t)TOK * DIM];    // src + proj(att) (fp32)
__device__ __half g_ffn [(size_t)TOK * FDIM];   // GELU(FFN1) (half)
__device__ int    g_msk [TOK];
// half weight copies
__device__ __half g_wq[(size_t)3*DIM*DIM];
__device__ __half g_wp[(size_t)DIM*DIM];
__device__ __half g_w1[(size_t)FDIM*DIM];
__device__ __half g_w2[(size_t)DIM*FDIM];

// ======================= small helpers =======================
__device__ __forceinline__ uint32_t smem_u32(const void* p) {
    uint32_t a;
    asm("{ .reg .u64 t; cvta.to.shared.u64 t, %1; cvt.u32.u64 %0, t; }" : "=r"(a) : "l"(p));
    return a;
}

__device__ __forceinline__ uint32_t h2_u32(__half2 h) {
    uint32_t u;
    memcpy(&u, &h, 4);
    return u;
}

__device__ __forceinline__ void mma_f16(float c[4],
                                        uint32_t a0, uint32_t a1, uint32_t a2, uint32_t a3,
                                        uint32_t b0, uint32_t b1) {
    asm volatile(
        "mma.sync.aligned.m16n8k16.row.col.f32.f16.f16.f32 "
        "{%0,%1,%2,%3}, {%4,%5,%6,%7}, {%8,%9}, {%0,%1,%2,%3};"
        : "+f"(c[0]), "+f"(c[1]), "+f"(c[2]), "+f"(c[3])
        : "r"(a0), "r"(a1), "r"(a2), "r"(a3), "r"(b0), "r"(b1));
}

#define LDSM_X4(r0, r1, r2, r3, addr) \
    asm volatile("ldmatrix.sync.aligned.m8n8.x4.shared.b16 {%0,%1,%2,%3}, [%4];" \
        : "=r"(r0), "=r"(r1), "=r"(r2), "=r"(r3) : "r"(addr))

#define LDSM_X4_T(r0, r1, r2, r3, addr) \
    asm volatile("ldmatrix.sync.aligned.m8n8.x4.trans.shared.b16 {%0,%1,%2,%3}, [%4];" \
        : "=r"(r0), "=r"(r1), "=r"(r2), "=r"(r3) : "r"(addr))

#define CP_ASYNC16(saddr, gptr) \
    asm volatile("cp.async.cg.shared.global [%0], [%1], 16;" :: "r"(saddr), "l"(gptr))
#define CP_COMMIT() asm volatile("cp.async.commit_group;")
#define CP_WAIT0()  asm volatile("cp.async.wait_group 0;")

__device__ __forceinline__ float gelu_f(float x)
{
    return 0.5f * x * (1.0f + erff(x * 0.70710678118654752f));
}

// ---------------- fp32 -> fp16 conversion of ALL weights in one launch ----------------
__global__ void cvt_all_kernel(const float4* __restrict__ i0, __half2* __restrict__ o0, int n0,
                               const float4* __restrict__ i1, __half2* __restrict__ o1, int n1,
                               const float4* __restrict__ i2, __half2* __restrict__ o2, int n2,
                               const float4* __restrict__ i3, __half2* __restrict__ o3, int n3)
{
    int idx = blockIdx.x * blockDim.x + threadIdx.x;
    const float4* in; __half2* out;
    if (idx < n0)              { in = i0; out = o0; }
    else if ((idx -= n0) < n1) { in = i1; out = o1; }
    else if ((idx -= n1) < n2) { in = i2; out = o2; }
    else if ((idx -= n2) < n3) { in = i3; out = o3; }
    else return;
    float4 v = in[idx];
    out[2*idx]   = __floats2half2_rn(v.x, v.y);
    out[2*idx+1] = __floats2half2_rn(v.z, v.w);
}

// ---------------- mask dtype detection + normalization ----------------
__global__ void mask_kernel(const unsigned char* __restrict__ raw, int* __restrict__ gm)
{
    __shared__ int cnt[4];
    int t = threadIdx.x;
    if (t < 4) cnt[t] = 0;
    __syncthreads();
    int l1=0, l2=0, l3=0, lb=0;
    for (int i = t; i < TOK; i += blockDim.x) {
        unsigned char bch = raw[i];
        if (bch) {
            int m = i & 3;
            if (m == 1) l1++;
            else if (m == 2) l2++;
            else if (m == 3) l3++;
            if (bch > 1) lb++;
        }
    }
    atomicAdd(&cnt[0], l1); atomicAdd(&cnt[1], l2);
    atomicAdd(&cnt[2], l3); atomicAdd(&cnt[3], lb);
    __syncthreads();
    int c1 = cnt[0], c2 = cnt[1], c3 = cnt[2], cb = cnt[3];
    int type;
    if (c1 < 64 && c2 < 64 && c3 < 64) type = 0;
    else if (c1 < 64)                  type = 1;
    else if (cb < 64)                  type = 2;
    else                               type = 3;
    for (int i = t; i < TOK; i += blockDim.x) {
        int v;
        if      (type == 0) v = (((const int*)raw)[i] != 0);
        else if (type == 1) v = (((const float*)raw)[i] != 0.0f);
        else if (type == 2) v = (raw[i] != 0);
        else                v = (((const unsigned short*)raw)[i] != 0);
        gm[i] = v;
    }
}

// ---------------- LayerNorm: half out ----------------
__global__ void ln_kernel(const float* __restrict__ in,
                          const float* __restrict__ gamma,
                          const float* __restrict__ beta,
                          __half* __restrict__ outh)
{
    int row = blockIdx.x;
    int t = threadIdx.x;
    const float* xr = in + (size_t)row * DIM;
    float4 v = ((const float4*)xr)[t];
    float s = v.x + v.y + v.z + v.w;
    float q = v.x*v.x + v.y*v.y + v.z*v.z + v.w*v.w;
    #pragma unroll
    for (int o = 16; o; o >>= 1) {
        s += __shfl_xor_sync(0xffffffffu, s, o);
        q += __shfl_xor_sync(0xffffffffu, q, o);
    }
    __shared__ float ss[8], qq[8];
    if ((t & 31) == 0) { ss[t >> 5] = s; qq[t >> 5] = q; }
    __syncthreads();
    s = 0.f; q = 0.f;
    #pragma unroll
    for (int i = 0; i < 8; i++) { s += ss[i]; q += qq[i]; }
    float mean = s * (1.0f / DIM);
    float var  = q * (1.0f / DIM) - mean * mean;
    float rstd = rsqrtf(var + 1e-5f);
    float4 gv = ((const float4*)gamma)[t];
    float4 bv = ((const float4*)beta)[t];
    float ox = (v.x - mean) * rstd * gv.x + bv.x;
    float oy = (v.y - mean) * rstd * gv.y + bv.y;
    float oz = (v.z - mean) * rstd * gv.z + bv.z;
    float ow = (v.w - mean) * rstd * gv.w + bv.w;
    __half2* oh = (__half2*)(outh + (size_t)row * DIM);
    oh[2*t]   = __floats2half2_rn(ox, oy);
    oh[2*t+1] = __floats2half2_rn(oz, ow);
}

// ======================= FP16 mma.sync GEMM — BK=64, single barrier/iter =======================
// C[M,N] = A[M,K] @ B[N,K]^T (+bias/gelu/res). 128x128 tile, 8 warps (2m x 4n),
// warp tile 64x32, m16n8k16, ldmatrix fragments. Row = 64 halves, stride 36 half2 (144B).
// SMEM: [A s0 | A s1 | B s0 | B s1] = 73728 B -> 2 CTAs/SM (228KB carveout).
#define SH2B 36
#define HST64 (128*SH2B)                  // half2 per matrix per stage (4608)
#define HST64_B (HST64*4)                 // stage bytes (18432)
#define GSMEM_BYTES (4*HST64*4)           // 73728

template<int N, int K, bool HAS_BIAS, bool HAS_GELU, bool HAS_RES, bool RES_HALF, bool OUT_HALF>
__global__ void __launch_bounds__(256, 2)
gemm_mma(const __half* __restrict__ A, const __half* __restrict__ Bm,
         const float* __restrict__ bias, const void* __restrict__ res,
         void* __restrict__ Cout)
{
    extern __shared__ __half2 sh[];
    __half2* As0 = sh;
    __half2* Bs0 = sh + 2*HST64;

    int tid  = threadIdx.x;
    int lane = tid & 31, warp = tid >> 5;
    int wm = warp >> 2, wn = warp & 3;
    int gid = lane >> 2, tig = lane & 3;
    int bm = blockIdx.y * 128, bn = blockIdx.x * 128;

    // loader: 128 rows x 8 segs (16B) per matrix = 1024 chunks, 4/thread
    int lrow = tid >> 3;          // 0..31
    int lseg = tid & 7;           // 0..7
    const __half* gA = A  + (size_t)(bm + lrow) * K + lseg * 8;
    const __half* gB = Bm + (size_t)(bn + lrow) * K + lseg * 8;
    uint32_t uA = smem_u32(&As0[lrow*SH2B + lseg*4]);
    uint32_t uB = smem_u32(&Bs0[lrow*SH2B + lseg*4]);
    const uint32_t SROW32 = 32u * SH2B * 4u;   // 4608 B
    const size_t  GROW32 = (size_t)32 * K;

    // ldmatrix per-lane addresses (stage 0 base; stage s = +s*HST64_B)
    int lane15 = lane & 15;
    int lq     = lane >> 4;
    uint32_t aAddr[4];
    #pragma unroll
    for (int mt = 0; mt < 4; mt++)
        aAddr[mt] = smem_u32(&As0[(wm*64 + mt*16 + lane15)*SH2B]) + lq*16;
    uint32_t bAddr[2];
    {
        int quad = lane >> 3;
        int l7   = lane & 7;
        #pragma unroll
        for (int p = 0; p < 2; p++) {
            int row = wn*32 + (2*p + (quad >> 1))*8 + l7;
            bAddr[p] = smem_u32(&Bs0[row*SH2B]) + (quad & 1)*16;
        }
    }

    float acc[4][4][4];
    #pragma unroll
    for (int mt = 0; mt < 4; mt++)
        #pragma unroll
        for (int nt = 0; nt < 4; nt++)
            #pragma unroll
            for (int e = 0; e < 4; e++) acc[mt][nt][e] = 0.f;

    const int KT = K / 64;

    // prologue: prefetch stage 0
    #pragma unroll
    for (int i = 0; i < 4; i++) {
        CP_ASYNC16(uA + i*SROW32, gA + i*GROW32);
        CP_ASYNC16(uB + i*SROW32, gB + i*GROW32);
    }
    CP_COMMIT();

    for (int kt = 0; kt < KT; kt++) {
        int cur = kt & 1;
        CP_WAIT0();
        __syncthreads();   // stage cur visible; all warps finished reading stage cur (iter kt-2)

        if (kt + 1 < KT) {
            int nxt = cur ^ 1;
            size_t go = (size_t)(kt + 1) * 64;
            uint32_t so = (uint32_t)nxt * HST64_B;
            #pragma unroll
            for (int i = 0; i < 4; i++) {
                CP_ASYNC16(uA + so + i*SROW32, gA + go + i*GROW32);
                CP_ASYNC16(uB + so + i*SROW32, gB + go + i*GROW32);
            }
            CP_COMMIT();
        }

        uint32_t stoff = (uint32_t)cur * HST64_B;
        #pragma unroll
        for (int ks = 0; ks < 4; ks++) {     // 4 x k16 per BK=64
            uint32_t ko = ks * 32;
            uint32_t af[4][4];
            #pragma unroll
            for (int mt = 0; mt < 4; mt++)
                LDSM_X4(af[mt][0], af[mt][1], af[mt][2], af[mt][3],
                        aAddr[mt] + stoff + ko);
            uint32_t bf[4][2];
            #pragma unroll
            for (int p = 0; p < 2; p++)
                LDSM_X4(bf[2*p][0], bf[2*p][1], bf[2*p+1][0], bf[2*p+1][1],
                        bAddr[p] + stoff + ko);
            #pragma unroll
            for (int mt = 0; mt < 4; mt++)
                #pragma unroll
                for (int nt = 0; nt < 4; nt++)
                    mma_f16(acc[mt][nt], af[mt][0], af[mt][1], af[mt][2], af[mt][3],
                            bf[nt][0], bf[nt][1]);
        }
    }

    #pragma unroll
    for (int mt = 0; mt < 4; mt++) {
        int row = bm + wm*64 + mt*16 + gid;
        #pragma unroll
        for (int nt = 0; nt < 4; nt++) {
            int col = bn + wn*32 + nt*8 + 2*tig;
            float2 bb = {0.f, 0.f};
            if (HAS_BIAS) bb = *(const float2*)&bias[col];
            #pragma unroll
            for (int half_ = 0; half_ < 2; half_++) {
                int rr = row + half_*8;
                float vx = acc[mt][nt][half_*2+0];
                float vy = acc[mt][nt][half_*2+1];
                if (HAS_BIAS) { vx += bb.x; vy += bb.y; }
                if (HAS_GELU) { vx = gelu_f(vx); vy = gelu_f(vy); }
                if (HAS_RES) {
                    if (RES_HALF) {
                        __half2 rh = *(const __half2*)((const __half*)res + (size_t)rr * N + col);
                        float2 rv = __half22float2(rh);
                        vx += rv.x; vy += rv.y;
                    } else {
                        float2 rv = *(const float2*)((const float*)res + (size_t)rr * N + col);
                        vx += rv.x; vy += rv.y;
                    }
                }
                if (OUT_HALF) {
                    __half2* cp = (__half2*)((__half*)Cout + (size_t)rr * N + col);
                    *cp = __floats2half2_rn(vx, vy);
                } else {
                    float2 o2 = {vx, vy};
                    *(float2*)((float*)Cout + (size_t)rr * N + col) = o2;
                }
            }
        }
    }
}

// ======================= fp16 flash attention — trans-LDSM V (proven R16) =======================
#define ASQ2  0
#define ASK2  4608
#define ASV2  9216
#define ASP2  16128
#define AH2TOT 20736
#define ATTN_BYTES (AH2TOT*4 + 2*64*4)   // 83456
#define KSTG_B (2304u*4u)                // K/V stage stride in bytes (9216)
#define VROW16 (16u*36u*4u)              // 16 V rows in bytes (2304)

__global__ void __launch_bounds__(256)
attn_mma(const __half* __restrict__ qkv, const int* __restrict__ gm,
         __half* __restrict__ outp)
{
    extern __shared__ __half2 S[];
    int* smk = (int*)(S + AH2TOT);

    const float SCALE = 0.125f;
    int tid = threadIdx.x, lane = tid & 31, warp = tid >> 5;
    int gid = lane >> 2, tig = lane & 3;
    int bh = blockIdx.y, b = bh >> 4, h = bh & 15;
    int q0 = blockIdx.x * 128;
    int qr = warp*16 + gid;

    {
        int r = tid >> 1;
        int sg = (tid & 1) * 4;
        const __half* qp = qkv + (size_t)(b*SEQ + q0 + r) * (3*DIM) + h*HDIM;
        #pragma unroll
        for (int j = 0; j < 4; j++) {
            uint4 w = ((const uint4*)qp)[sg + j];
            *(uint4*)&S[ASQ2 + r*36 + (sg + j)*4] = w;
        }
    }

    auto issue_tile = [&](int kt, int st) {
        int tokbase = b*SEQ + kt*64;
        #pragma unroll
        for (int i = 0; i < 2; i++) {
            int c   = tid + i*256;
            int row = c >> 3;
            int seg = c & 7;
            const __half* kg = qkv + (size_t)(tokbase + row) * (3*DIM) + DIM + h*HDIM + seg*8;
            CP_ASYNC16(smem_u32(&S[ASK2 + st*2304 + row*36 + seg*4]), kg);
            CP_ASYNC16(smem_u32(&S[ASV2 + st*2304 + row*36 + seg*4]), kg + DIM);
        }
        if (tid < 16) {
            CP_ASYNC16(smem_u32(&smk[st*64 + tid*4]), gm + tokbase + tid*4);
        }
    };

    issue_tile(0, 0);
    CP_COMMIT();

    int mq0 = gm[b*SEQ + q0 + qr];
    int mq1 = gm[b*SEQ + q0 + qr + 8];

    float m0 = -FLT_MAX, m1 = -FLT_MAX, l0 = 0.f, l1 = 0.f;
    float acc[8][4];
    #pragma unroll
    for (int nt = 0; nt < 8; nt++)
        acc[nt][0] = acc[nt][1] = acc[nt][2] = acc[nt][3] = 0.f;

    uint32_t* p_u = (uint32_t*)(S + ASP2);

    int lane15 = lane & 15;
    int lq     = lane >> 4;
    uint32_t aQ = smem_u32(&S[ASQ2 + (warp*16 + lane15)*36]) + lq*16;
    uint32_t aP = smem_u32(&S[ASP2 + (warp*16 + lane15)*36]) + lq*16;
    int quad = lane >> 3;
    int l7   = lane & 7;
    uint32_t bK[4];
    #pragma unroll
    for (int p = 0; p < 4; p++) {
        int row = (2*p + (quad >> 1))*8 + l7;
        bK[p] = smem_u32(&S[ASK2 + row*36]) + (quad & 1)*16;
    }
    uint32_t bV[4];
    #pragma unroll
    for (int p = 0; p < 4; p++) {
        int vrow = (quad & 1)*8 + l7;
        bV[p] = smem_u32(&S[ASV2 + vrow*36]) + 32*p + (quad >> 1)*16;
    }

    for (int kt = 0; kt < 16; kt++) {
        int s = kt & 1;
        CP_WAIT0();
        __syncthreads();

        if (kt < 15) { issue_tile(kt+1, s^1); CP_COMMIT(); }

        float sc[8][4];
        #pragma unroll
        for (int nt = 0; nt < 8; nt++)
            sc[nt][0] = sc[nt][1] = sc[nt][2] = sc[nt][3] = 0.f;
        {
            uint32_t stg = (uint32_t)s * KSTG_B;
            #pragma unroll
            for (int ks = 0; ks < 4; ks++) {
                uint32_t ko = ks * 32;
                uint32_t a0, a1, a2, a3;
                LDSM_X4(a0, a1, a2, a3, aQ + ko);
                #pragma unroll
                for (int p = 0; p < 4; p++) {
                    uint32_t b0, b1, b2, b3;
                    LDSM_X4(b0, b1, b2, b3, bK[p] + stg + ko);
                    mma_f16(sc[2*p],   a0, a1, a2, a3, b0, b1);
                    mma_f16(sc[2*p+1], a0, a1, a2, a3, b2, b3);
                }
            }
        }

        float mx0 = -FLT_MAX, mx1 = -FLT_MAX;
        #pragma unroll
        for (int nt = 0; nt < 8; nt++) {
            int kk = 8*nt + 2*tig;
            int ka_ = smk[s*64 + kk], kb_ = smk[s*64 + kk + 1];
            sc[nt][0] = (mq0 && ka_) ? sc[nt][0]*SCALE : -FLT_MAX;
            sc[nt][1] = (mq0 && kb_) ? sc[nt][1]*SCALE : -FLT_MAX;
            sc[nt][2] = (mq1 && ka_) ? sc[nt][2]*SCALE : -FLT_MAX;
            sc[nt][3] = (mq1 && kb_) ? sc[nt][3]*SCALE : -FLT_MAX;
            mx0 = fmaxf(mx0, fmaxf(sc[nt][0], sc[nt][1]));
            mx1 = fmaxf(mx1, fmaxf(sc[nt][2], sc[nt][3]));
        }
        mx0 = fmaxf(mx0, __shfl_xor_sync(0xffffffffu, mx0, 1));
        mx0 = fmaxf(mx0, __shfl_xor_sync(0xffffffffu, mx0, 2));
        mx1 = fmaxf(mx1, __shfl_xor_sync(0xffffffffu, mx1, 1));
        mx1 = fmaxf(mx1, __shfl_xor_sync(0xffffffffu, mx1, 2));

        float mn0 = fmaxf(m0, mx0), mn1 = fmaxf(m1, mx1);
        float c0 = __expf(m0 - mn0), c1 = __expf(m1 - mn1);
        float ps0 = 0.f, ps1 = 0.f;
        #pragma unroll
        for (int nt = 0; nt < 8; nt++) {
            float p00 = __expf(sc[nt][0] - mn0);
            float p01 = __expf(sc[nt][1] - mn0);
            float p10 = __expf(sc[nt][2] - mn1);
            float p11 = __expf(sc[nt][3] - mn1);
            ps0 += p00 + p01; ps1 += p10 + p11;
            int cp = 4*nt + tig;
            p_u[qr*36 + cp]     = h2_u32(__floats2half2_rn(p00, p01));
            p_u[(qr+8)*36 + cp] = h2_u32(__floats2half2_rn(p10, p11));
        }
        ps0 += __shfl_xor_sync(0xffffffffu, ps0, 1);
        ps0 += __shfl_xor_sync(0xffffffffu, ps0, 2);
        ps1 += __shfl_xor_sync(0xffffffffu, ps1, 1);
        ps1 += __shfl_xor_sync(0xffffffffu, ps1, 2);
        l0 = l0*c0 + ps0; l1 = l1*c1 + ps1;
        m0 = mn0; m1 = mn1;
        #pragma unroll
        for (int nt = 0; nt < 8; nt++) {
            acc[nt][0] *= c0; acc[nt][1] *= c0;
            acc[nt][2] *= c1; acc[nt][3] *= c1;
        }
        __syncwarp();

        {
            uint32_t stg = (uint32_t)s * KSTG_B;
            #pragma unroll
            for (int ks = 0; ks < 4; ks++) {
                uint32_t ko = ks * 32;
                uint32_t vo = ks * VROW16;
                uint32_t a0, a1, a2, a3;
                LDSM_X4(a0, a1, a2, a3, aP + ko);
                #pragma unroll
                for (int p = 0; p < 4; p++) {
                    uint32_t b0, b1, b2, b3;
                    LDSM_X4_T(b0, b1, b2, b3, bV[p] + stg + vo);
                    mma_f16(acc[2*p],   a0, a1, a2, a3, b0, b1);
                    mma_f16(acc[2*p+1], a0, a1, a2, a3, b2, b3);
                }
            }
        }
    }

    float inv0 = 1.0f / l0, inv1 = 1.0f / l1;
    __half2* op0 = (__half2*)(outp + (size_t)(b*SEQ + q0 + qr) * DIM + h*HDIM);
    __half2* op1 = (__half2*)(outp + (size_t)(b*SEQ + q0 + qr + 8) * DIM + h*HDIM);
    #pragma unroll
    for (int nt = 0; nt < 8; nt++) {
        int cp = 4*nt + tig;
        op0[cp] = __floats2half2_rn(acc[nt][0]*inv0, acc[nt][1]*inv0);
        op1[cp] = __floats2half2_rn(acc[nt][2]*inv1, acc[nt][3]*inv1);
    }
}

// ======================= host side =======================
extern "C" void kernel_launch(void* const* d_in, const int* in_sizes, int n_in,
                              void* d_out, int out_size)
{
    const float* src   = (const float*)d_in[0];
    const unsigned char* maskraw = (const unsigned char*)d_in[1];
    const float* Wqkv  = (const float*)d_in[2];
    const float* Wproj = (const float*)d_in[3];
    const float* bproj = (const float*)d_in[4];
    const float* W1    = (const float*)d_in[5];
    const float* b1    = (const float*)d_in[6];
    const float* W2    = (const float*)d_in[7];
    const float* b2    = (const float*)d_in[8];
    const float* g0    = (const float*)d_in[9];
    const float* beta0 = (const float*)d_in[10];
    const float* g1    = (const float*)d_in[11];
    const float* beta1 = (const float*)d_in[12];
    float* out = (float*)d_out;

    __half *ln, *qkv, *att, *ffn, *wq, *wp, *w1c, *w2c;
    float *x; int* msk;
    cudaGetSymbolAddress((void**)&ln,   g_ln);
    cudaGetSymbolAddress((void**)&qkv,  g_qkv);
    cudaGetSymbolAddress((void**)&att,  g_att);
    cudaGetSymbolAddress((void**)&x,    g_x);
    cudaGetSymbolAddress((void**)&ffn,  g_ffn);
    cudaGetSymbolAddress((void**)&msk,  g_msk);
    cudaGetSymbolAddress((void**)&wq,   g_wq);
    cudaGetSymbolAddress((void**)&wp,   g_wp);
    cudaGetSymbolAddress((void**)&w1c,  g_w1);
    cudaGetSymbolAddress((void**)&w2c,  g_w2);

    cudaFuncSetAttribute(attn_mma, cudaFuncAttributeMaxDynamicSharedMemorySize, ATTN_BYTES);
    cudaFuncSetAttribute(gemm_mma<3*DIM, DIM,  false, false, false, false, true>,
                         cudaFuncAttributeMaxDynamicSharedMemorySize, GSMEM_BYTES);
    cudaFuncSetAttribute(gemm_mma<DIM,   DIM,  true,  false, true,  false, false>,
                         cudaFuncAttributeMaxDynamicSharedMemorySize, GSMEM_BYTES);
    cudaFuncSetAttribute(gemm_mma<FDIM,  DIM,  true,  true,  false, false, true>,
                         cudaFuncAttributeMaxDynamicSharedMemorySize, GSMEM_BYTES);
    cudaFuncSetAttribute(gemm_mma<DIM,   FDIM, true,  false, true,  true,  false>,
                         cudaFuncAttributeMaxDynamicSharedMemorySize, GSMEM_BYTES);

    // 0. weights -> fp16 (one launch)
    {
        int n0 = 3*DIM*DIM/4, n1 = DIM*DIM/4, n2 = FDIM*DIM/4, n3 = DIM*FDIM/4;
        int ntot = n0 + n1 + n2 + n3;
        cvt_all_kernel<<<(ntot + 255)/256, 256>>>(
            (const float4*)Wqkv,  (__half2*)wq,  n0,
            (const float4*)Wproj, (__half2*)wp,  n1,
            (const float4*)W1,    (__half2*)w1c, n2,
            (const float4*)W2,    (__half2*)w2c, n3);
    }
    // 1. normalize mask
    mask_kernel<<<1, 256>>>(maskraw, msk);
    // 2. LN0 (half out)
    ln_kernel<<<TOK, 256>>>(src, g0, beta0, ln);
    // 3. QKV projection -> half
    gemm_mma<3*DIM, DIM, false, false, false, false, true>
        <<<dim3(3*DIM/128, TOK/128), 256, GSMEM_BYTES>>>(ln, wq, nullptr, nullptr, qkv);
    // 4. attention (fp16 tensor-core flash, half out)
    attn_mma<<<dim3(SEQ/128, BATCH*NHEAD), 256, ATTN_BYTES>>>(qkv, msk, att);
    // 5. output projection + bias + residual(src fp32) -> x (fp32)
    gemm_mma<DIM, DIM, true, false, true, false, false>
        <<<dim3(DIM/128, TOK/128), 256, GSMEM_BYTES>>>(att, wp, bproj, src, x);
    // 6. LN1 (half out; also serves as FFN2 residual)
    ln_kernel<<<TOK, 256>>>(x, g1, beta1, ln);
    // 7. FFN1 + bias + exact GELU -> half
    gemm_mma<FDIM, DIM, true, true, false, false, true>
        <<<dim3(FDIM/128, TOK/128), 256, GSMEM_BYTES>>>(ln, w1c, b1, nullptr, ffn);
    // 8. FFN2 + bias + residual(LN1 half) -> out (fp32)
    gemm_mma<DIM, FDIM, true, false, true, true, false>
        <<<dim3(DIM/128, TOK/128), 256, GSMEM_BYTES>>>(ffn, w2c, b2, ln, out);
}